// round 12
// baseline (speedup 1.0000x reference)
#include <cuda_runtime.h>
#include <cuda_fp16.h>
#include <cstdint>
#include <math.h>

// Problem constants
#define BSZ   2
#define SEQ   2048
#define DIM   2048
#define NH    16
#define DRr   64
#define DNn   64
#define DQK   128
#define DVv   128
#define QLR   1536
#define KVLR  1024
#define ROWS  (BSZ*SEQ)          // 4096
#define KVAW  (KVLR + DRr)       // 1088
#define KV2W  (NH*(DNn+DVv))     // 3072
#define QW    (NH*DQK)           // 2048
#define OW    (NH*DVv)           // 2048

// -------- fp32 scratch --------
__device__ float g_qa  [ (size_t)ROWS * QLR  ];
__device__ float g_kv  [ (size_t)ROWS * KVAW ];

// -------- fp16 operands --------
__device__ __half g_xh   [(size_t)ROWS*DIM];
__device__ __half g_wqa  [(size_t)QLR*DIM];
__device__ __half g_wqb  [(size_t)QW*QLR];
__device__ __half g_wkva [(size_t)KVAW*DIM];
__device__ __half g_wkvb [(size_t)KV2W*KVLR];
__device__ __half g_wo16 [(size_t)DIM*OW];
__device__ __half g_qanh [(size_t)ROWS*QLR];
__device__ __half g_ckvnh[(size_t)ROWS*KVLR];
__device__ __half g_ath  [(size_t)ROWS*OW];
__device__ __half g_qh   [(size_t)ROWS*QW];
__device__ __half g_khi  [(size_t)ROWS*QW];
__device__ __half g_vhi  [(size_t)ROWS*OW];

// ============================================================
// helpers (sm_80-compatible instructions only — plain sm_103 target!)
// ============================================================
__device__ __forceinline__ uint32_t smem_u32(const void* p) {
    uint32_t a;
    asm("{ .reg .u64 t; cvta.to.shared.u64 t, %1; cvt.u32.u64 %0, t; }" : "=r"(a) : "l"(p));
    return a;
}

#define CP16(dst, src) \
    asm volatile("cp.async.cg.shared.global [%0], [%1], 16;" :: "r"(dst), "l"(src))
#define CP_COMMIT() asm volatile("cp.async.commit_group;" ::: "memory")
#define CP_WAIT(n)  asm volatile("cp.async.wait_group %0;" :: "n"(n) : "memory")

#define LDSM4(r0, r1, r2, r3, addr) \
    asm volatile("ldmatrix.sync.aligned.m8n8.x4.shared.b16 {%0,%1,%2,%3}, [%4];" \
        : "=r"(r0), "=r"(r1), "=r"(r2), "=r"(r3) : "r"(addr))

#define LDSM4T(r0, r1, r2, r3, addr) \
    asm volatile("ldmatrix.sync.aligned.m8n8.x4.trans.shared.b16 {%0,%1,%2,%3}, [%4];" \
        : "=r"(r0), "=r"(r1), "=r"(r2), "=r"(r3) : "r"(addr))

#define MMA_F16(d, a, b0, b1) \
    asm volatile("mma.sync.aligned.m16n8k16.row.col.f32.f16.f16.f32 " \
        "{%0,%1,%2,%3},{%4,%5,%6,%7},{%8,%9},{%0,%1,%2,%3};" \
        : "+f"((d)[0]), "+f"((d)[1]), "+f"((d)[2]), "+f"((d)[3]) \
        : "r"((a)[0]), "r"((a)[1]), "r"((a)[2]), "r"((a)[3]), "r"(b0), "r"(b1))

// ============================================================
// batched fp32->fp16 convert: 6 segments in ONE launch
// ============================================================
struct ConvSegs {
    const float4* src[6];
    uint2*        dst[6];
    int           end4[6];   // cumulative end offsets (float4 units)
};

__global__ void conv_batch_kernel(ConvSegs segs, int total4)
{
    int i = blockIdx.x * blockDim.x + threadIdx.x;
    if (i >= total4) return;
    int s = 0;
#pragma unroll
    for (int k = 0; k < 5; k++) s += (i >= segs.end4[k]);
    const int base = (s == 0) ? 0 : segs.end4[s - 1];
    const int off  = i - base;
    float4 v = segs.src[s][off];
    __half2 h0 = __floats2half2_rn(v.x, v.y);
    __half2 h1 = __floats2half2_rn(v.z, v.w);
    segs.dst[s][off] = make_uint2(*(uint32_t*)&h0, *(uint32_t*)&h1);
}

// RMSNorm: fp32 in (strided) -> fp16 out, vectorized
__global__ void rmsnorm_h_kernel(const float* __restrict__ in, const float* __restrict__ w,
                                 __half* __restrict__ out, int K, int inStride)
{
    const int row = blockIdx.x;
    const float4* ip4 = (const float4*)(in + (size_t)row * inStride);
    const float4* w4  = (const float4*)w;
    uint2* op4 = (uint2*)(out + (size_t)row * K);
    const int K4 = K >> 2;

    float ss = 0.f;
    for (int i = threadIdx.x; i < K4; i += blockDim.x) {
        float4 v = ip4[i];
        ss += v.x * v.x + v.y * v.y + v.z * v.z + v.w * v.w;
    }
#pragma unroll
    for (int o = 16; o; o >>= 1) ss += __shfl_xor_sync(0xffffffffu, ss, o);

    __shared__ float red[8];
    __shared__ float rs;
    int wid = threadIdx.x >> 5, lid = threadIdx.x & 31;
    if (lid == 0) red[wid] = ss;
    __syncthreads();
    if (threadIdx.x == 0) {
        float t = 0.f;
        for (int i = 0; i < 8; i++) t += red[i];
        rs = rsqrtf(t / (float)K + 1e-6f);
    }
    __syncthreads();
    float r = rs;
    for (int i = threadIdx.x; i < K4; i += blockDim.x) {
        float4 v = ip4[i];
        float4 ww = w4[i];
        __half2 h0 = __floats2half2_rn(v.x * r * ww.x, v.y * r * ww.y);
        __half2 h1 = __floats2half2_rn(v.z * r * ww.z, v.w * r * ww.w);
        op4[i] = make_uint2(*(uint32_t*)&h0, *(uint32_t*)&h1);
    }
}

// Fill rotated k_pe into g_khi cols [h*128+64, h*128+128): one warp per row.
__global__ void fill_kpe_kernel(const float* __restrict__ fcos, const float* __restrict__ fsin)
{
    const int row = blockIdx.x;
    const int lane = threadIdx.x;       // 32
    const int s = row & (SEQ - 1);
    float x0 = g_kv[(size_t)row * KVAW + KVLR + 2 * lane];
    float x1 = g_kv[(size_t)row * KVAW + KVLR + 2 * lane + 1];
    float c = fcos[s * 32 + lane], sn = fsin[s * 32 + lane];
    __half2 pe = __floats2half2_rn(x0 * c - x1 * sn, x0 * sn + x1 * c);
#pragma unroll
    for (int h = 0; h < NH; h++)
        *(__half2*)&g_khi[(size_t)row * QW + h * DQK + DNn + 2 * lane] = pe;
}

// ============================================================
// single-term fp16 GEMM via mma.sync: C = A[M,K] @ W[N,K]^T
// 128x128x32 tiles, 3-stage cp.async pipeline, 8 warps (4m x 2n), occ 2.
// EPI = 0: fp32 C row-major (bounds-checked)
// EPI = 1: fused RoPE on d>=64 of each 128-head-slice + fp16 -> Hq (N=2048)
// EPI = 2: fused scatter of kv2 cols -> Hk (k_nope) / Hv (v), fp16 (N=3072)
// ============================================================
#define GBM 128
#define GBN 128
#define ROWB 80
#define MAT_BYTES (128 * ROWB)         // 10240
#define OFF_A   0
#define OFF_W   (1 * MAT_BYTES)
#define STAGE_BYTES (2 * MAT_BYTES)    // 20480
#define NSTAGE 3
#define GS_TOTAL (NSTAGE * STAGE_BYTES) // 61440

template<int EPI>
__global__ void __launch_bounds__(256, 2)
gemm_mma(const __half* __restrict__ A, const __half* __restrict__ W,
         float* __restrict__ C, __half* __restrict__ Hq,
         __half* __restrict__ Hk, __half* __restrict__ Hv,
         int N, int K,
         const float* __restrict__ fcos, const float* __restrict__ fsin)
{
    extern __shared__ char smx[];
    const uint32_t sb = smem_u32(smx);
    const int tid  = threadIdx.x;
    const int lane = tid & 31;
    const int warp = tid >> 5;
    const int wm = warp >> 1, wn = warp & 1;
    const int m0 = blockIdx.y * GBM;
    const int n0 = blockIdx.x * GBN;

    const int lrow = tid & 127;
    const int lc   = tid >> 7;
    const size_t a_g = (size_t)(m0 + lrow) * K;
    int wr = n0 + lrow; if (wr >= N) wr = N - 1;
    const size_t w_g = (size_t)wr * K;
    const uint32_t s_row = (uint32_t)lrow * ROWB;

    const uint32_t a_lm = (uint32_t)(wm * 32 + (lane & 15)) * ROWB + (uint32_t)(lane >> 4) * 16;
    const uint32_t b_lm = (uint32_t)(wn * 64 + (lane & 7) + ((lane >> 4) << 3)) * ROWB
                        + (uint32_t)((lane >> 3) & 1) * 16;

    float acc[2][8][4];
#pragma unroll
    for (int i = 0; i < 2; i++)
#pragma unroll
        for (int j = 0; j < 8; j++)
#pragma unroll
            for (int q = 0; q < 4; q++) acc[i][j][q] = 0.f;

    const int nch = K >> 5;

    // prologue: chunks 0,1 into stages 0,1
#pragma unroll
    for (int p = 0; p < NSTAGE - 1; p++) {
        const int k0 = p << 5;
        const uint32_t st = sb + p * STAGE_BYTES + s_row;
#pragma unroll
        for (int u = 0; u < 2; u++) {
            const int cc = lc + u * 2;
            CP16(st + OFF_A + cc * 16, A + a_g + k0 + cc * 8);
            CP16(st + OFF_W + cc * 16, W + w_g + k0 + cc * 8);
        }
        CP_COMMIT();
    }

    int stage = 0;
    for (int c = 0; c < nch; c++) {
        CP_WAIT(NSTAGE - 2);
        __syncthreads();

        if (c + NSTAGE - 1 < nch) {
            const int k0 = (c + NSTAGE - 1) << 5;
            int ws = stage + NSTAGE - 1; if (ws >= NSTAGE) ws -= NSTAGE;
            const uint32_t st = sb + ws * STAGE_BYTES + s_row;
#pragma unroll
            for (int u = 0; u < 2; u++) {
                const int cc = lc + u * 2;
                CP16(st + OFF_A + cc * 16, A + a_g + k0 + cc * 8);
                CP16(st + OFF_W + cc * 16, W + w_g + k0 + cc * 8);
            }
        }
        CP_COMMIT();

        const uint32_t base = sb + stage * STAGE_BYTES;
#pragma unroll
        for (int kk = 0; kk < 2; kk++) {
            uint32_t a[2][4], bh[4][4];
#pragma unroll
            for (int i = 0; i < 2; i++) {
                const uint32_t ao = base + OFF_A + a_lm + i * (16 * ROWB) + kk * 32;
                LDSM4(a[i][0], a[i][1], a[i][2], a[i][3], ao);
            }
#pragma unroll
            for (int g = 0; g < 4; g++) {
                const uint32_t bo = base + OFF_W + b_lm + g * (16 * ROWB) + kk * 32;
                LDSM4(bh[g][0], bh[g][1], bh[g][2], bh[g][3], bo);
            }
#pragma unroll
            for (int i = 0; i < 2; i++) {
#pragma unroll
                for (int j = 0; j < 8; j++) {
                    const int g = j >> 1, h = (j & 1) * 2;
                    MMA_F16(acc[i][j], a[i], bh[g][h], bh[g][h + 1]);
                }
            }
        }
        if (++stage == NSTAGE) stage = 0;
    }

    // ---- epilogue ----
#pragma unroll
    for (int i = 0; i < 2; i++) {
        const int row  = m0 + wm * 32 + i * 16 + (lane >> 2);
        const int row2 = row + 8;
#pragma unroll
        for (int j = 0; j < 8; j++) {
            const int col = n0 + wn * 64 + j * 8 + 2 * (lane & 3);
            float a0 = acc[i][j][0], a1 = acc[i][j][1];
            float b0 = acc[i][j][2], b1 = acc[i][j][3];

            if (EPI == 0) {
                if (col < N) {
                    *(float2*)&C[(size_t)row  * N + col] = make_float2(a0, a1);
                    *(float2*)&C[(size_t)row2 * N + col] = make_float2(b0, b1);
                }
            } else if (EPI == 1) {
                const int d = col & 127;
                if (d >= DNn) {
                    const int ir = (d - DNn) >> 1;
                    const int s0 = row & (SEQ - 1), s1 = row2 & (SEQ - 1);
                    float c0 = fcos[s0 * 32 + ir], sn0 = fsin[s0 * 32 + ir];
                    float c1 = fcos[s1 * 32 + ir], sn1 = fsin[s1 * 32 + ir];
                    float t0 = a0 * c0 - a1 * sn0, t1 = a0 * sn0 + a1 * c0;
                    a0 = t0; a1 = t1;
                    t0 = b0 * c1 - b1 * sn1; t1 = b0 * sn1 + b1 * c1;
                    b0 = t0; b1 = t1;
                }
                *(__half2*)&Hq[(size_t)row  * QW + col] = __floats2half2_rn(a0, a1);
                *(__half2*)&Hq[(size_t)row2 * QW + col] = __floats2half2_rn(b0, b1);
            } else {
                const int h = col / (DNn + DVv);
                const int d = col - h * (DNn + DVv);
                if (d < DNn) {
                    const size_t off = (size_t)h * DQK + d;
                    *(__half2*)&Hk[(size_t)row  * QW + off] = __floats2half2_rn(a0, a1);
                    *(__half2*)&Hk[(size_t)row2 * QW + off] = __floats2half2_rn(b0, b1);
                } else {
                    const size_t off = (size_t)h * DVv + (d - DNn);
                    *(__half2*)&Hv[(size_t)row  * OW + off] = __floats2half2_rn(a0, a1);
                    *(__half2*)&Hv[(size_t)row2 * OW + off] = __floats2half2_rn(b0, b1);
                }
            }
        }
    }
}

// ============================================================
// Flash attention — FA2-style, fp16 mma.sync, occupancy 3
// BQ=64, BK=64, 4 warps (each owns 16 rows), block 128.
// Longest-first CTA ordering (qt reversed) to pack the causal tail.
// Q fragments in registers; K + V in 2-stage cp.async ring; prefetch of
// tile kt+2 into the CURRENT stage strictly after the post-compute sync.
// grid: (SEQ/64, NH, BSZ)
// ============================================================
#define RB 272
#define SK    0
#define SV    17408
#define FSTG  34816                   // per stage: K + V
#define F_TOTAL (2 * FSTG)            // 69632

__global__ void __launch_bounds__(128, 3)
flash_mma(const __half* __restrict__ q16,
          const __half* __restrict__ khi, const __half* __restrict__ vhi)
{
    extern __shared__ char smx[];
    const uint32_t sb = smem_u32(smx);
    const int tid = threadIdx.x, lane = tid & 31, wid = tid >> 5;   // 4 warps
    const int qt = gridDim.x - 1 - blockIdx.x;   // longest CTAs first
    const int q0 = qt * 64;
    const int h  = blockIdx.y;
    const int b  = blockIdx.z;
    const float scale = 0.088388347648318447f;  // 128^-0.5

    const uint32_t a_off  = (uint32_t)(wid * 16 + (lane & 15)) * RB + (uint32_t)(lane >> 4) * 16;
    const uint32_t bK_off = (uint32_t)((lane & 7) + ((lane >> 4) << 3)) * RB
                          + (uint32_t)((lane >> 3) & 1) * 16;
    const uint32_t bV_off = (uint32_t)((lane & 7) + (((lane >> 3) & 1) << 3)) * RB
                          + (uint32_t)(lane >> 4) * 16;

    // ---- stage Q tile (64 x 128) through smem stage-0, hoist fragments
    {
        int r = tid >> 4;
        const int cc = tid & 15;
#pragma unroll
        for (int it = 0; it < 8; it++, r += 8) {
            size_t go = (size_t)(b * SEQ + q0 + r) * QW + h * DQK + cc * 8;
            *(uint4*)(smx + (uint32_t)r * RB + cc * 16) = *(const uint4*)(q16 + go);
        }
    }
    __syncthreads();
    uint32_t aq[8][4];
#pragma unroll
    for (int kk = 0; kk < 8; kk++)
        LDSM4(aq[kk][0], aq[kk][1], aq[kk][2], aq[kk][3], sb + a_off + kk * 32);
    __syncthreads();

    float oacc[16][4];
#pragma unroll
    for (int t = 0; t < 16; t++)
#pragma unroll
        for (int qq = 0; qq < 4; qq++) oacc[t][qq] = 0.f;
    float m0 = -1e30f, m1 = -1e30f, l0 = 0.f, l1 = 0.f;

    const int row0 = q0 + wid * 16 + (lane >> 2);
    const int row1 = row0 + 8;

    const int nkt = qt + 1;
    const int ldr_r0 = tid >> 4;        // 8 rows per pass, 8 passes
    const int ldr_c  = tid & 15;

    // prologue: tiles 0,1 into stages 0,1 (empty commit when nkt==1)
#pragma unroll
    for (int p = 0; p < 2; p++) {
        if (p < nkt) {
            const uint32_t stg = sb + p * FSTG;
            int r = ldr_r0;
#pragma unroll
            for (int it = 0; it < 8; it++, r += 8) {
                size_t grow = (size_t)(b * SEQ + p * 64 + r);
                size_t gk = grow * QW + h * DQK + ldr_c * 8;
                size_t gv = grow * OW + h * DVv + ldr_c * 8;
                uint32_t so = (uint32_t)r * RB + ldr_c * 16;
                CP16(stg + SK + so, khi + gk);
                CP16(stg + SV + so, vhi + gv);
            }
        }
        CP_COMMIT();
    }

    int stage = 0;
    for (int kt = 0; kt < nkt; kt++) {
        const int t0 = kt * 64;
        CP_WAIT(1);                    // tile kt resident
        __syncthreads();               // make it visible to all warps

        const uint32_t stg = sb + stage * FSTG;

        // ---- S = Q @ K^T  (warp tile 16 x 64)
        float sacc[8][4];
#pragma unroll
        for (int t = 0; t < 8; t++)
#pragma unroll
            for (int qq = 0; qq < 4; qq++) sacc[t][qq] = 0.f;

#pragma unroll
        for (int kk = 0; kk < 8; kk++) {
#pragma unroll
            for (int g = 0; g < 4; g++) {
                uint32_t bh[4];
                const uint32_t bo = bK_off + g * (16 * RB) + kk * 32;
                LDSM4(bh[0], bh[1], bh[2], bh[3], stg + SK + bo);
                MMA_F16(sacc[2*g],   aq[kk], bh[0], bh[1]);
                MMA_F16(sacc[2*g+1], aq[kk], bh[2], bh[3]);
            }
        }

        // ---- scale + causal mask
        const int cb = t0 + 2 * (lane & 3);
#pragma unroll
        for (int t = 0; t < 8; t++) {
            const int c0 = cb + 8 * t, c1 = c0 + 1;
            sacc[t][0] = sacc[t][0] * scale + ((c0 > row0) ? -1e9f : 0.f);
            sacc[t][1] = sacc[t][1] * scale + ((c1 > row0) ? -1e9f : 0.f);
            sacc[t][2] = sacc[t][2] * scale + ((c0 > row1) ? -1e9f : 0.f);
            sacc[t][3] = sacc[t][3] * scale + ((c1 > row1) ? -1e9f : 0.f);
        }

        // ---- online softmax
        float mx0 = -1e30f, mx1 = -1e30f;
#pragma unroll
        for (int t = 0; t < 8; t++) {
            mx0 = fmaxf(mx0, fmaxf(sacc[t][0], sacc[t][1]));
            mx1 = fmaxf(mx1, fmaxf(sacc[t][2], sacc[t][3]));
        }
        mx0 = fmaxf(mx0, __shfl_xor_sync(0xffffffffu, mx0, 1));
        mx0 = fmaxf(mx0, __shfl_xor_sync(0xffffffffu, mx0, 2));
        mx1 = fmaxf(mx1, __shfl_xor_sync(0xffffffffu, mx1, 1));
        mx1 = fmaxf(mx1, __shfl_xor_sync(0xffffffffu, mx1, 2));

        const float mn0 = fmaxf(m0, mx0), mn1 = fmaxf(m1, mx1);
        const float al0 = __expf(m0 - mn0), al1 = __expf(m1 - mn1);
        m0 = mn0; m1 = mn1;

        float ps0 = 0.f, ps1 = 0.f;
#pragma unroll
        for (int t = 0; t < 8; t++) {
            sacc[t][0] = __expf(sacc[t][0] - mn0);
            sacc[t][1] = __expf(sacc[t][1] - mn0);
            sacc[t][2] = __expf(sacc[t][2] - mn1);
            sacc[t][3] = __expf(sacc[t][3] - mn1);
            ps0 += sacc[t][0] + sacc[t][1];
            ps1 += sacc[t][2] + sacc[t][3];
        }
        ps0 += __shfl_xor_sync(0xffffffffu, ps0, 1);
        ps0 += __shfl_xor_sync(0xffffffffu, ps0, 2);
        ps1 += __shfl_xor_sync(0xffffffffu, ps1, 1);
        ps1 += __shfl_xor_sync(0xffffffffu, ps1, 2);
        l0 = l0 * al0 + ps0;
        l1 = l1 * al1 + ps1;

#pragma unroll
        for (int t = 0; t < 16; t++) {
            oacc[t][0] *= al0; oacc[t][1] *= al0;
            oacc[t][2] *= al1; oacc[t][3] *= al1;
        }

        // ---- O += P @ V
#pragma unroll
        for (int jj = 0; jj < 4; jj++) {
            const int t2 = 2 * jj, t3 = 2 * jj + 1;
            uint32_t phi[4];
            {
                __half2 h0 = __floats2half2_rn(sacc[t2][0], sacc[t2][1]);
                __half2 h1 = __floats2half2_rn(sacc[t2][2], sacc[t2][3]);
                __half2 h2 = __floats2half2_rn(sacc[t3][0], sacc[t3][1]);
                __half2 h3 = __floats2half2_rn(sacc[t3][2], sacc[t3][3]);
                phi[0] = *(uint32_t*)&h0; phi[1] = *(uint32_t*)&h1;
                phi[2] = *(uint32_t*)&h2; phi[3] = *(uint32_t*)&h3;
            }
#pragma unroll
            for (int g = 0; g < 8; g++) {
                uint32_t bv[4];
                const uint32_t bo = bV_off + jj * (16 * RB) + g * 32;
                LDSM4T(bv[0], bv[1], bv[2], bv[3], stg + SV + bo);
                MMA_F16(oacc[2*g],   phi, bv[0], bv[1]);
                MMA_F16(oacc[2*g+1], phi, bv[2], bv[3]);
            }
        }

        // ---- stage fully consumed by ALL warps: now prefetch tile kt+2 into it
        __syncthreads();
        if (kt + 2 < nkt) {
            int r = ldr_r0;
#pragma unroll
            for (int it = 0; it < 8; it++, r += 8) {
                size_t grow = (size_t)(b * SEQ + (kt + 2) * 64 + r);
                size_t gk = grow * QW + h * DQK + ldr_c * 8;
                size_t gv = grow * OW + h * DVv + ldr_c * 8;
                uint32_t so = stg + (uint32_t)r * RB + ldr_c * 16;
                CP16(so + SK, khi + gk);
                CP16(so + SV, vhi + gv);
            }
        }
        CP_COMMIT();
        stage ^= 1;
    }

    // ---- epilogue: write fp16 attn directly (A operand of final GEMM)
    const float inv0 = 1.f / l0, inv1 = 1.f / l1;
    const size_t o0 = (size_t)(b * SEQ + row0) * OW + h * DVv;
    const size_t o1 = (size_t)(b * SEQ + row1) * OW + h * DVv;
#pragma unroll
    for (int t = 0; t < 16; t++) {
        const int d0 = 8 * t + 2 * (lane & 3);
        __half2 v0 = __floats2half2_rn(oacc[t][0] * inv0, oacc[t][1] * inv0);
        __half2 v1 = __floats2half2_rn(oacc[t][2] * inv1, oacc[t][3] * inv1);
        *(__half2*)&g_ath[o0 + d0] = v0;
        *(__half2*)&g_ath[o1 + d0] = v1;
    }
}

// ============================================================
// launch
// ============================================================
extern "C" void kernel_launch(void* const* d_in, const int* in_sizes, int n_in,
                              void* d_out, int out_size)
{
    const float* x      = (const float*)d_in[0];
    const float* wq_a   = (const float*)d_in[1];
    const float* qnw    = (const float*)d_in[2];
    const float* wq_b   = (const float*)d_in[3];
    const float* wkv_a  = (const float*)d_in[4];
    const float* kvnw   = (const float*)d_in[5];
    const float* wkv_b  = (const float*)d_in[6];
    const float* wo     = (const float*)d_in[7];
    const float* fcos   = (const float*)d_in[9];
    const float* fsin   = (const float*)d_in[10];

    float* out = (float*)d_out;

    float *p_qa, *p_kv;
    cudaGetSymbolAddress((void**)&p_qa,   g_qa);
    cudaGetSymbolAddress((void**)&p_kv,   g_kv);

    __half *xh, *wqa, *wqb, *wka, *wkb, *wo16, *qanh, *ckvnh, *ath, *qh, *khi, *vhi;
    cudaGetSymbolAddress((void**)&xh,   g_xh);
    cudaGetSymbolAddress((void**)&wqa,  g_wqa);
    cudaGetSymbolAddress((void**)&wqb,  g_wqb);
    cudaGetSymbolAddress((void**)&wka,  g_wkva);
    cudaGetSymbolAddress((void**)&wkb,  g_wkvb);
    cudaGetSymbolAddress((void**)&wo16, g_wo16);
    cudaGetSymbolAddress((void**)&qanh, g_qanh);
    cudaGetSymbolAddress((void**)&ckvnh,g_ckvnh);
    cudaGetSymbolAddress((void**)&ath,  g_ath);
    cudaGetSymbolAddress((void**)&qh,   g_qh);
    cudaGetSymbolAddress((void**)&khi,  g_khi);
    cudaGetSymbolAddress((void**)&vhi,  g_vhi);

    cudaFuncSetAttribute(gemm_mma<0>, cudaFuncAttributeMaxDynamicSharedMemorySize, GS_TOTAL);
    cudaFuncSetAttribute(gemm_mma<1>, cudaFuncAttributeMaxDynamicSharedMemorySize, GS_TOTAL);
    cudaFuncSetAttribute(gemm_mma<2>, cudaFuncAttributeMaxDynamicSharedMemorySize, GS_TOTAL);
    cudaFuncSetAttribute(flash_mma,   cudaFuncAttributeMaxDynamicSharedMemorySize, F_TOTAL);

    // operand prep: ONE batched convert launch (6 segments)
    {
        ConvSegs segs;
        const int n0 = (ROWS * DIM) / 4;
        const int n1 = (QLR * DIM) / 4;
        const int n2 = (QW * QLR) / 4;
        const int n3 = (KVAW * DIM) / 4;
        const int n4 = (KV2W * KVLR) / 4;
        const int n5 = (DIM * OW) / 4;
        segs.src[0] = (const float4*)x;     segs.dst[0] = (uint2*)xh;
        segs.src[1] = (const float4*)wq_a;  segs.dst[1] = (uint2*)wqa;
        segs.src[2] = (const float4*)wq_b;  segs.dst[2] = (uint2*)wqb;
        segs.src[3] = (const float4*)wkv_a; segs.dst[3] = (uint2*)wka;
        segs.src[4] = (const float4*)wkv_b; segs.dst[4] = (uint2*)wkb;
        segs.src[5] = (const float4*)wo;    segs.dst[5] = (uint2*)wo16;
        segs.end4[0] = n0;
        segs.end4[1] = n0 + n1;
        segs.end4[2] = n0 + n1 + n2;
        segs.end4[3] = n0 + n1 + n2 + n3;
        segs.end4[4] = n0 + n1 + n2 + n3 + n4;
        segs.end4[5] = n0 + n1 + n2 + n3 + n4 + n5;
        const int total4 = segs.end4[5];
        conv_batch_kernel<<<(total4 + 255) / 256, 256>>>(segs, total4);
    }

    // q path
    gemm_mma<0><<<dim3(QLR / 128, ROWS / 128), 256, GS_TOTAL>>>(
        xh, wqa, p_qa, nullptr, nullptr, nullptr, QLR, DIM, fcos, fsin);
    rmsnorm_h_kernel<<<ROWS, 256>>>(p_qa, qnw, qanh, QLR, QLR);
    gemm_mma<1><<<dim3(QW / 128, ROWS / 128), 256, GS_TOTAL>>>(
        qanh, wqb, nullptr, qh, nullptr, nullptr, QW, QLR, fcos, fsin);

    // kv path
    gemm_mma<0><<<dim3((KVAW + 127) / 128, ROWS / 128), 256, GS_TOTAL>>>(
        xh, wka, p_kv, nullptr, nullptr, nullptr, KVAW, DIM, fcos, fsin);
    rmsnorm_h_kernel<<<ROWS, 256>>>(p_kv, kvnw, ckvnh, KVLR, KVAW);
    gemm_mma<2><<<dim3(KV2W / 128, ROWS / 128), 256, GS_TOTAL>>>(
        ckvnh, wkb, nullptr, nullptr, khi, vhi, KV2W, KVLR, fcos, fsin);
    fill_kpe_kernel<<<ROWS, 32>>>(fcos, fsin);

    // attention (tensor-core flash, occ 3, longest-first)
    flash_mma<<<dim3(SEQ / 64, NH, BSZ), 128, F_TOTAL>>>(qh, khi, vhi);

    // output projection
    gemm_mma<0><<<dim3(DIM / 128, ROWS / 128), 256, GS_TOTAL>>>(
        ath, wo16, out, nullptr, nullptr, nullptr, DIM, OW, fcos, fsin);
}

// round 13
// speedup vs baseline: 1.0149x; 1.0149x over previous
#include <cuda_runtime.h>
#include <cuda_fp16.h>
#include <cstdint>
#include <math.h>

// Problem constants
#define BSZ   2
#define SEQ   2048
#define DIM   2048
#define NH    16
#define DRr   64
#define DNn   64
#define DQK   128
#define DVv   128
#define QLR   1536
#define KVLR  1024
#define ROWS  (BSZ*SEQ)          // 4096
#define KVAW  (KVLR + DRr)       // 1088
#define KV2W  (NH*(DNn+DVv))     // 3072
#define QW    (NH*DQK)           // 2048
#define OW    (NH*DVv)           // 2048

// -------- fp32 scratch --------
__device__ float g_qa  [ (size_t)ROWS * QLR  ];
__device__ float g_kv  [ (size_t)ROWS * KVAW ];

// -------- fp16 operands --------
__device__ __half g_xh   [(size_t)ROWS*DIM];
__device__ __half g_wqa  [(size_t)QLR*DIM];
__device__ __half g_wqb  [(size_t)QW*QLR];
__device__ __half g_wkva [(size_t)KVAW*DIM];
__device__ __half g_wkvb [(size_t)KV2W*KVLR];
__device__ __half g_wo16 [(size_t)DIM*OW];
__device__ __half g_qanh [(size_t)ROWS*QLR];
__device__ __half g_ckvnh[(size_t)ROWS*KVLR];
__device__ __half g_ath  [(size_t)ROWS*OW];
__device__ __half g_qh   [(size_t)ROWS*QW];
__device__ __half g_khi  [(size_t)ROWS*QW];
__device__ __half g_vhi  [(size_t)ROWS*OW];

// ============================================================
// helpers (sm_80-compatible instructions only — plain sm_103 target!)
// ============================================================
__device__ __forceinline__ uint32_t smem_u32(const void* p) {
    uint32_t a;
    asm("{ .reg .u64 t; cvta.to.shared.u64 t, %1; cvt.u32.u64 %0, t; }" : "=r"(a) : "l"(p));
    return a;
}

#define CP16(dst, src) \
    asm volatile("cp.async.cg.shared.global [%0], [%1], 16;" :: "r"(dst), "l"(src))
#define CP_COMMIT() asm volatile("cp.async.commit_group;" ::: "memory")
#define CP_WAIT(n)  asm volatile("cp.async.wait_group %0;" :: "n"(n) : "memory")

#define LDSM4(r0, r1, r2, r3, addr) \
    asm volatile("ldmatrix.sync.aligned.m8n8.x4.shared.b16 {%0,%1,%2,%3}, [%4];" \
        : "=r"(r0), "=r"(r1), "=r"(r2), "=r"(r3) : "r"(addr))

#define LDSM4T(r0, r1, r2, r3, addr) \
    asm volatile("ldmatrix.sync.aligned.m8n8.x4.trans.shared.b16 {%0,%1,%2,%3}, [%4];" \
        : "=r"(r0), "=r"(r1), "=r"(r2), "=r"(r3) : "r"(addr))

#define MMA_F16(d, a, b0, b1) \
    asm volatile("mma.sync.aligned.m16n8k16.row.col.f32.f16.f16.f32 " \
        "{%0,%1,%2,%3},{%4,%5,%6,%7},{%8,%9},{%0,%1,%2,%3};" \
        : "+f"((d)[0]), "+f"((d)[1]), "+f"((d)[2]), "+f"((d)[3]) \
        : "r"((a)[0]), "r"((a)[1]), "r"((a)[2]), "r"((a)[3]), "r"(b0), "r"(b1))

// ============================================================
// elementwise kernels (vectorized: 4 elems/thread)
// ============================================================
__global__ void conv_h4_kernel(const float4* __restrict__ in, uint2* __restrict__ out, int n4)
{
    int i = blockIdx.x * blockDim.x + threadIdx.x;
    if (i < n4) {
        float4 v = in[i];
        __half2 h0 = __floats2half2_rn(v.x, v.y);
        __half2 h1 = __floats2half2_rn(v.z, v.w);
        out[i] = make_uint2(*(uint32_t*)&h0, *(uint32_t*)&h1);
    }
}

// RMSNorm: fp32 in (strided) -> fp16 out, vectorized
__global__ void rmsnorm_h_kernel(const float* __restrict__ in, const float* __restrict__ w,
                                 __half* __restrict__ out, int K, int inStride)
{
    const int row = blockIdx.x;
    const float4* ip4 = (const float4*)(in + (size_t)row * inStride);
    const float4* w4  = (const float4*)w;
    uint2* op4 = (uint2*)(out + (size_t)row * K);
    const int K4 = K >> 2;

    float ss = 0.f;
    for (int i = threadIdx.x; i < K4; i += blockDim.x) {
        float4 v = ip4[i];
        ss += v.x * v.x + v.y * v.y + v.z * v.z + v.w * v.w;
    }
#pragma unroll
    for (int o = 16; o; o >>= 1) ss += __shfl_xor_sync(0xffffffffu, ss, o);

    __shared__ float red[8];
    __shared__ float rs;
    int wid = threadIdx.x >> 5, lid = threadIdx.x & 31;
    if (lid == 0) red[wid] = ss;
    __syncthreads();
    if (threadIdx.x == 0) {
        float t = 0.f;
        for (int i = 0; i < 8; i++) t += red[i];
        rs = rsqrtf(t / (float)K + 1e-6f);
    }
    __syncthreads();
    float r = rs;
    for (int i = threadIdx.x; i < K4; i += blockDim.x) {
        float4 v = ip4[i];
        float4 ww = w4[i];
        __half2 h0 = __floats2half2_rn(v.x * r * ww.x, v.y * r * ww.y);
        __half2 h1 = __floats2half2_rn(v.z * r * ww.z, v.w * r * ww.w);
        op4[i] = make_uint2(*(uint32_t*)&h0, *(uint32_t*)&h1);
    }
}

// Fill rotated k_pe into g_khi cols [h*128+64, h*128+128) for all heads.
__global__ void fill_kpe_kernel(const float* __restrict__ fcos, const float* __restrict__ fsin)
{
    const int row = blockIdx.x;
    const int tid = threadIdx.x;        // 256
    __shared__ float pe[64];
    const int s = row & (SEQ - 1);
    if (tid < 32) {
        float x0 = g_kv[(size_t)row * KVAW + KVLR + 2 * tid];
        float x1 = g_kv[(size_t)row * KVAW + KVLR + 2 * tid + 1];
        float c = fcos[s * 32 + tid], sn = fsin[s * 32 + tid];
        pe[2 * tid]     = x0 * c - x1 * sn;
        pe[2 * tid + 1] = x0 * sn + x1 * c;
    }
    __syncthreads();
#pragma unroll
    for (int l = 0; l < 2; l++) {
        int idx = tid + l * 256;        // 0..511: h = idx>>5, pair = idx&31
        int h = idx >> 5, pr = idx & 31;
        *(__half2*)&g_khi[(size_t)row * QW + h * DQK + DNn + 2 * pr] =
            __floats2half2_rn(pe[2 * pr], pe[2 * pr + 1]);
    }
}

// ============================================================
// single-term fp16 GEMM via mma.sync: C = A[M,K] @ W[N,K]^T
// 128x128x64 tiles, 3-stage cp.async pipeline, 8 warps (4m x 2n), occ 2.
// BK=64: half the barrier rounds vs BK=32 (latency-bound per R12 profile).
// EPI = 0: fp32 C row-major (bounds-checked)
// EPI = 1: fused RoPE on d>=64 of each 128-head-slice + fp16 -> Hq (N=2048)
// EPI = 2: fused scatter of kv2 cols -> Hk (k_nope) / Hv (v), fp16 (N=3072)
// ============================================================
#define GBM 128
#define GBN 128
#define ROWB 144                       // 64 halfs (128B) + 16B pad
#define MAT_BYTES (128 * ROWB)         // 18432
#define OFF_A   0
#define OFF_W   (1 * MAT_BYTES)
#define STAGE_BYTES (2 * MAT_BYTES)    // 36864
#define NSTAGE 3
#define GS_TOTAL (NSTAGE * STAGE_BYTES) // 110592

template<int EPI>
__global__ void __launch_bounds__(256, 2)
gemm_mma(const __half* __restrict__ A, const __half* __restrict__ W,
         float* __restrict__ C, __half* __restrict__ Hq,
         __half* __restrict__ Hk, __half* __restrict__ Hv,
         int N, int K,
         const float* __restrict__ fcos, const float* __restrict__ fsin)
{
    extern __shared__ char smx[];
    const uint32_t sb = smem_u32(smx);
    const int tid  = threadIdx.x;
    const int lane = tid & 31;
    const int warp = tid >> 5;
    const int wm = warp >> 1, wn = warp & 1;
    const int m0 = blockIdx.y * GBM;
    const int n0 = blockIdx.x * GBN;

    const int lrow = tid & 127;
    const int lc   = tid >> 7;
    const size_t a_g = (size_t)(m0 + lrow) * K;
    int wr = n0 + lrow; if (wr >= N) wr = N - 1;
    const size_t w_g = (size_t)wr * K;
    const uint32_t s_row = (uint32_t)lrow * ROWB;

    const uint32_t a_lm = (uint32_t)(wm * 32 + (lane & 15)) * ROWB + (uint32_t)(lane >> 4) * 16;
    const uint32_t b_lm = (uint32_t)(wn * 64 + (lane & 7) + ((lane >> 4) << 3)) * ROWB
                        + (uint32_t)((lane >> 3) & 1) * 16;

    float acc[2][8][4];
#pragma unroll
    for (int i = 0; i < 2; i++)
#pragma unroll
        for (int j = 0; j < 8; j++)
#pragma unroll
            for (int q = 0; q < 4; q++) acc[i][j][q] = 0.f;

    const int nch = K >> 6;           // BK = 64

    // prologue: chunks 0,1 into stages 0,1
#pragma unroll
    for (int p = 0; p < NSTAGE - 1; p++) {
        const int k0 = p << 6;
        const uint32_t st = sb + p * STAGE_BYTES + s_row;
#pragma unroll
        for (int u = 0; u < 4; u++) {
            const int cc = lc + u * 2;        // 0..7 16B-chunks per 128B row
            CP16(st + OFF_A + cc * 16, A + a_g + k0 + cc * 8);
            CP16(st + OFF_W + cc * 16, W + w_g + k0 + cc * 8);
        }
        CP_COMMIT();
    }

    int stage = 0;
    for (int c = 0; c < nch; c++) {
        CP_WAIT(NSTAGE - 2);
        __syncthreads();

        if (c + NSTAGE - 1 < nch) {
            const int k0 = (c + NSTAGE - 1) << 6;
            int ws = stage + NSTAGE - 1; if (ws >= NSTAGE) ws -= NSTAGE;
            const uint32_t st = sb + ws * STAGE_BYTES + s_row;
#pragma unroll
            for (int u = 0; u < 4; u++) {
                const int cc = lc + u * 2;
                CP16(st + OFF_A + cc * 16, A + a_g + k0 + cc * 8);
                CP16(st + OFF_W + cc * 16, W + w_g + k0 + cc * 8);
            }
        }
        CP_COMMIT();

        const uint32_t base = sb + stage * STAGE_BYTES;
#pragma unroll
        for (int kk = 0; kk < 4; kk++) {
            uint32_t a[2][4], bh[4][4];
#pragma unroll
            for (int i = 0; i < 2; i++) {
                const uint32_t ao = base + OFF_A + a_lm + i * (16 * ROWB) + kk * 32;
                LDSM4(a[i][0], a[i][1], a[i][2], a[i][3], ao);
            }
#pragma unroll
            for (int g = 0; g < 4; g++) {
                const uint32_t bo = base + OFF_W + b_lm + g * (16 * ROWB) + kk * 32;
                LDSM4(bh[g][0], bh[g][1], bh[g][2], bh[g][3], bo);
            }
#pragma unroll
            for (int i = 0; i < 2; i++) {
#pragma unroll
                for (int j = 0; j < 8; j++) {
                    const int g = j >> 1, h = (j & 1) * 2;
                    MMA_F16(acc[i][j], a[i], bh[g][h], bh[g][h + 1]);
                }
            }
        }
        if (++stage == NSTAGE) stage = 0;
    }

    // ---- epilogue ----
#pragma unroll
    for (int i = 0; i < 2; i++) {
        const int row  = m0 + wm * 32 + i * 16 + (lane >> 2);
        const int row2 = row + 8;
#pragma unroll
        for (int j = 0; j < 8; j++) {
            const int col = n0 + wn * 64 + j * 8 + 2 * (lane & 3);
            float a0 = acc[i][j][0], a1 = acc[i][j][1];
            float b0 = acc[i][j][2], b1 = acc[i][j][3];

            if (EPI == 0) {
                if (col < N) {
                    *(float2*)&C[(size_t)row  * N + col] = make_float2(a0, a1);
                    *(float2*)&C[(size_t)row2 * N + col] = make_float2(b0, b1);
                }
            } else if (EPI == 1) {
                const int d = col & 127;
                if (d >= DNn) {
                    const int ir = (d - DNn) >> 1;
                    const int s0 = row & (SEQ - 1), s1 = row2 & (SEQ - 1);
                    float c0 = fcos[s0 * 32 + ir], sn0 = fsin[s0 * 32 + ir];
                    float c1 = fcos[s1 * 32 + ir], sn1 = fsin[s1 * 32 + ir];
                    float t0 = a0 * c0 - a1 * sn0, t1 = a0 * sn0 + a1 * c0;
                    a0 = t0; a1 = t1;
                    t0 = b0 * c1 - b1 * sn1; t1 = b0 * sn1 + b1 * c1;
                    b0 = t0; b1 = t1;
                }
                *(__half2*)&Hq[(size_t)row  * QW + col] = __floats2half2_rn(a0, a1);
                *(__half2*)&Hq[(size_t)row2 * QW + col] = __floats2half2_rn(b0, b1);
            } else {
                const int h = col / (DNn + DVv);
                const int d = col - h * (DNn + DVv);
                if (d < DNn) {
                    const size_t off = (size_t)h * DQK + d;
                    *(__half2*)&Hk[(size_t)row  * QW + off] = __floats2half2_rn(a0, a1);
                    *(__half2*)&Hk[(size_t)row2 * QW + off] = __floats2half2_rn(b0, b1);
                } else {
                    const size_t off = (size_t)h * DVv + (d - DNn);
                    *(__half2*)&Hv[(size_t)row  * OW + off] = __floats2half2_rn(a0, a1);
                    *(__half2*)&Hv[(size_t)row2 * OW + off] = __floats2half2_rn(b0, b1);
                }
            }
        }
    }
}

// ============================================================
// Flash attention — FA2-style, fp16 mma.sync, occupancy 3
// BQ=64, BK=64, 4 warps (each owns 16 rows), block 128.
// Q fragments in registers; K + V in 2-stage cp.async ring; prefetch of
// tile kt+2 into the CURRENT stage strictly after the post-compute sync.
// grid: (SEQ/64, NH, BSZ)
// ============================================================
#define RB 272
#define SK    0
#define SV    17408
#define FSTG  34816                   // per stage: K + V
#define F_TOTAL (2 * FSTG)            // 69632

__global__ void __launch_bounds__(128, 3)
flash_mma(const __half* __restrict__ q16,
          const __half* __restrict__ khi, const __half* __restrict__ vhi)
{
    extern __shared__ char smx[];
    const uint32_t sb = smem_u32(smx);
    const int tid = threadIdx.x, lane = tid & 31, wid = tid >> 5;   // 4 warps
    const int q0 = blockIdx.x * 64;
    const int h  = blockIdx.y;
    const int b  = blockIdx.z;
    const float scale = 0.088388347648318447f;  // 128^-0.5

    const uint32_t a_off  = (uint32_t)(wid * 16 + (lane & 15)) * RB + (uint32_t)(lane >> 4) * 16;
    const uint32_t bK_off = (uint32_t)((lane & 7) + ((lane >> 4) << 3)) * RB
                          + (uint32_t)((lane >> 3) & 1) * 16;
    const uint32_t bV_off = (uint32_t)((lane & 7) + (((lane >> 3) & 1) << 3)) * RB
                          + (uint32_t)(lane >> 4) * 16;

    // ---- stage Q tile (64 x 128) through smem stage-0, hoist fragments
    {
        int r = tid >> 4;
        const int cc = tid & 15;
#pragma unroll
        for (int it = 0; it < 8; it++, r += 8) {
            size_t go = (size_t)(b * SEQ + q0 + r) * QW + h * DQK + cc * 8;
            *(uint4*)(smx + (uint32_t)r * RB + cc * 16) = *(const uint4*)(q16 + go);
        }
    }
    __syncthreads();
    uint32_t aq[8][4];
#pragma unroll
    for (int kk = 0; kk < 8; kk++)
        LDSM4(aq[kk][0], aq[kk][1], aq[kk][2], aq[kk][3], sb + a_off + kk * 32);
    __syncthreads();

    float oacc[16][4];
#pragma unroll
    for (int t = 0; t < 16; t++)
#pragma unroll
        for (int qq = 0; qq < 4; qq++) oacc[t][qq] = 0.f;
    float m0 = -1e30f, m1 = -1e30f, l0 = 0.f, l1 = 0.f;

    const int row0 = q0 + wid * 16 + (lane >> 2);
    const int row1 = row0 + 8;

    const int nkt = blockIdx.x + 1;
    const int ldr_r0 = tid >> 4;        // 8 rows per pass, 8 passes
    const int ldr_c  = tid & 15;

    // prologue: tiles 0,1 into stages 0,1 (empty commit when nkt==1)
#pragma unroll
    for (int p = 0; p < 2; p++) {
        if (p < nkt) {
            const uint32_t stg = sb + p * FSTG;
            int r = ldr_r0;
#pragma unroll
            for (int it = 0; it < 8; it++, r += 8) {
                size_t grow = (size_t)(b * SEQ + p * 64 + r);
                size_t gk = grow * QW + h * DQK + ldr_c * 8;
                size_t gv = grow * OW + h * DVv + ldr_c * 8;
                uint32_t so = (uint32_t)r * RB + ldr_c * 16;
                CP16(stg + SK + so, khi + gk);
                CP16(stg + SV + so, vhi + gv);
            }
        }
        CP_COMMIT();
    }

    int stage = 0;
    for (int kt = 0; kt < nkt; kt++) {
        const int t0 = kt * 64;
        CP_WAIT(1);                    // tile kt resident
        __syncthreads();               // make it visible to all warps

        const uint32_t stg = sb + stage * FSTG;

        // ---- S = Q @ K^T  (warp tile 16 x 64)
        float sacc[8][4];
#pragma unroll
        for (int t = 0; t < 8; t++)
#pragma unroll
            for (int qq = 0; qq < 4; qq++) sacc[t][qq] = 0.f;

#pragma unroll
        for (int kk = 0; kk < 8; kk++) {
#pragma unroll
            for (int g = 0; g < 4; g++) {
                uint32_t bh[4];
                const uint32_t bo = bK_off + g * (16 * RB) + kk * 32;
                LDSM4(bh[0], bh[1], bh[2], bh[3], stg + SK + bo);
                MMA_F16(sacc[2*g],   aq[kk], bh[0], bh[1]);
                MMA_F16(sacc[2*g+1], aq[kk], bh[2], bh[3]);
            }
        }

        // ---- scale + causal mask
        const int cb = t0 + 2 * (lane & 3);
#pragma unroll
        for (int t = 0; t < 8; t++) {
            const int c0 = cb + 8 * t, c1 = c0 + 1;
            sacc[t][0] = sacc[t][0] * scale + ((c0 > row0) ? -1e9f : 0.f);
            sacc[t][1] = sacc[t][1] * scale + ((c1 > row0) ? -1e9f : 0.f);
            sacc[t][2] = sacc[t][2] * scale + ((c0 > row1) ? -1e9f : 0.f);
            sacc[t][3] = sacc[t][3] * scale + ((c1 > row1) ? -1e9f : 0.f);
        }

        // ---- online softmax
        float mx0 = -1e30f, mx1 = -1e30f;
#pragma unroll
        for (int t = 0; t < 8; t++) {
            mx0 = fmaxf(mx0, fmaxf(sacc[t][0], sacc[t][1]));
            mx1 = fmaxf(mx1, fmaxf(sacc[t][2], sacc[t][3]));
        }
        mx0 = fmaxf(mx0, __shfl_xor_sync(0xffffffffu, mx0, 1));
        mx0 = fmaxf(mx0, __shfl_xor_sync(0xffffffffu, mx0, 2));
        mx1 = fmaxf(mx1, __shfl_xor_sync(0xffffffffu, mx1, 1));
        mx1 = fmaxf(mx1, __shfl_xor_sync(0xffffffffu, mx1, 2));

        const float mn0 = fmaxf(m0, mx0), mn1 = fmaxf(m1, mx1);
        const float al0 = __expf(m0 - mn0), al1 = __expf(m1 - mn1);
        m0 = mn0; m1 = mn1;

        float ps0 = 0.f, ps1 = 0.f;
#pragma unroll
        for (int t = 0; t < 8; t++) {
            sacc[t][0] = __expf(sacc[t][0] - mn0);
            sacc[t][1] = __expf(sacc[t][1] - mn0);
            sacc[t][2] = __expf(sacc[t][2] - mn1);
            sacc[t][3] = __expf(sacc[t][3] - mn1);
            ps0 += sacc[t][0] + sacc[t][1];
            ps1 += sacc[t][2] + sacc[t][3];
        }
        ps0 += __shfl_xor_sync(0xffffffffu, ps0, 1);
        ps0 += __shfl_xor_sync(0xffffffffu, ps0, 2);
        ps1 += __shfl_xor_sync(0xffffffffu, ps1, 1);
        ps1 += __shfl_xor_sync(0xffffffffu, ps1, 2);
        l0 = l0 * al0 + ps0;
        l1 = l1 * al1 + ps1;

#pragma unroll
        for (int t = 0; t < 16; t++) {
            oacc[t][0] *= al0; oacc[t][1] *= al0;
            oacc[t][2] *= al1; oacc[t][3] *= al1;
        }

        // ---- O += P @ V
#pragma unroll
        for (int jj = 0; jj < 4; jj++) {
            const int t2 = 2 * jj, t3 = 2 * jj + 1;
            uint32_t phi[4];
            {
                __half2 h0 = __floats2half2_rn(sacc[t2][0], sacc[t2][1]);
                __half2 h1 = __floats2half2_rn(sacc[t2][2], sacc[t2][3]);
                __half2 h2 = __floats2half2_rn(sacc[t3][0], sacc[t3][1]);
                __half2 h3 = __floats2half2_rn(sacc[t3][2], sacc[t3][3]);
                phi[0] = *(uint32_t*)&h0; phi[1] = *(uint32_t*)&h1;
                phi[2] = *(uint32_t*)&h2; phi[3] = *(uint32_t*)&h3;
            }
#pragma unroll
            for (int g = 0; g < 8; g++) {
                uint32_t bv[4];
                const uint32_t bo = bV_off + jj * (16 * RB) + g * 32;
                LDSM4T(bv[0], bv[1], bv[2], bv[3], stg + SV + bo);
                MMA_F16(oacc[2*g],   phi, bv[0], bv[1]);
                MMA_F16(oacc[2*g+1], phi, bv[2], bv[3]);
            }
        }

        // ---- stage fully consumed by ALL warps: now prefetch tile kt+2 into it
        __syncthreads();
        if (kt + 2 < nkt) {
            int r = ldr_r0;
#pragma unroll
            for (int it = 0; it < 8; it++, r += 8) {
                size_t grow = (size_t)(b * SEQ + (kt + 2) * 64 + r);
                size_t gk = grow * QW + h * DQK + ldr_c * 8;
                size_t gv = grow * OW + h * DVv + ldr_c * 8;
                uint32_t so = stg + (uint32_t)r * RB + ldr_c * 16;
                CP16(so + SK, khi + gk);
                CP16(so + SV, vhi + gv);
            }
        }
        CP_COMMIT();
        stage ^= 1;
    }

    // ---- epilogue: write fp16 attn directly (A operand of final GEMM)
    const float inv0 = 1.f / l0, inv1 = 1.f / l1;
    const size_t o0 = (size_t)(b * SEQ + row0) * OW + h * DVv;
    const size_t o1 = (size_t)(b * SEQ + row1) * OW + h * DVv;
#pragma unroll
    for (int t = 0; t < 16; t++) {
        const int d0 = 8 * t + 2 * (lane & 3);
        __half2 v0 = __floats2half2_rn(oacc[t][0] * inv0, oacc[t][1] * inv0);
        __half2 v1 = __floats2half2_rn(oacc[t][2] * inv1, oacc[t][3] * inv1);
        *(__half2*)&g_ath[o0 + d0] = v0;
        *(__half2*)&g_ath[o1 + d0] = v1;
    }
}

// ============================================================
// launch
// ============================================================
static inline void convw(const float* in, __half* out, size_t n)
{
    conv_h4_kernel<<<(int)((n / 4 + 255) / 256), 256>>>(
        (const float4*)in, (uint2*)out, (int)(n / 4));
}

extern "C" void kernel_launch(void* const* d_in, const int* in_sizes, int n_in,
                              void* d_out, int out_size)
{
    const float* x      = (const float*)d_in[0];
    const float* wq_a   = (const float*)d_in[1];
    const float* qnw    = (const float*)d_in[2];
    const float* wq_b   = (const float*)d_in[3];
    const float* wkv_a  = (const float*)d_in[4];
    const float* kvnw   = (const float*)d_in[5];
    const float* wkv_b  = (const float*)d_in[6];
    const float* wo     = (const float*)d_in[7];
    const float* fcos   = (const float*)d_in[9];
    const float* fsin   = (const float*)d_in[10];

    float* out = (float*)d_out;

    float *p_qa, *p_kv;
    cudaGetSymbolAddress((void**)&p_qa,   g_qa);
    cudaGetSymbolAddress((void**)&p_kv,   g_kv);

    __half *xh, *wqa, *wqb, *wka, *wkb, *wo16, *qanh, *ckvnh, *ath, *qh, *khi, *vhi;
    cudaGetSymbolAddress((void**)&xh,   g_xh);
    cudaGetSymbolAddress((void**)&wqa,  g_wqa);
    cudaGetSymbolAddress((void**)&wqb,  g_wqb);
    cudaGetSymbolAddress((void**)&wka,  g_wkva);
    cudaGetSymbolAddress((void**)&wkb,  g_wkvb);
    cudaGetSymbolAddress((void**)&wo16, g_wo16);
    cudaGetSymbolAddress((void**)&qanh, g_qanh);
    cudaGetSymbolAddress((void**)&ckvnh,g_ckvnh);
    cudaGetSymbolAddress((void**)&ath,  g_ath);
    cudaGetSymbolAddress((void**)&qh,   g_qh);
    cudaGetSymbolAddress((void**)&khi,  g_khi);
    cudaGetSymbolAddress((void**)&vhi,  g_vhi);

    cudaFuncSetAttribute(gemm_mma<0>, cudaFuncAttributeMaxDynamicSharedMemorySize, GS_TOTAL);
    cudaFuncSetAttribute(gemm_mma<1>, cudaFuncAttributeMaxDynamicSharedMemorySize, GS_TOTAL);
    cudaFuncSetAttribute(gemm_mma<2>, cudaFuncAttributeMaxDynamicSharedMemorySize, GS_TOTAL);
    cudaFuncSetAttribute(flash_mma,   cudaFuncAttributeMaxDynamicSharedMemorySize, F_TOTAL);

    // operand prep (all single fp16, separate launches — R12's batching regressed)
    convw(x,     xh,   (size_t)ROWS * DIM);
    convw(wq_a,  wqa,  (size_t)QLR * DIM);
    convw(wq_b,  wqb,  (size_t)QW * QLR);
    convw(wkv_a, wka,  (size_t)KVAW * DIM);
    convw(wkv_b, wkb,  (size_t)KV2W * KVLR);
    convw(wo,    wo16, (size_t)DIM * OW);

    // q path
    gemm_mma<0><<<dim3(QLR / 128, ROWS / 128), 256, GS_TOTAL>>>(
        xh, wqa, p_qa, nullptr, nullptr, nullptr, QLR, DIM, fcos, fsin);
    rmsnorm_h_kernel<<<ROWS, 256>>>(p_qa, qnw, qanh, QLR, QLR);
    gemm_mma<1><<<dim3(QW / 128, ROWS / 128), 256, GS_TOTAL>>>(
        qanh, wqb, nullptr, qh, nullptr, nullptr, QW, QLR, fcos, fsin);

    // kv path
    gemm_mma<0><<<dim3((KVAW + 127) / 128, ROWS / 128), 256, GS_TOTAL>>>(
        xh, wka, p_kv, nullptr, nullptr, nullptr, KVAW, DIM, fcos, fsin);
    rmsnorm_h_kernel<<<ROWS, 256>>>(p_kv, kvnw, ckvnh, KVLR, KVAW);
    gemm_mma<2><<<dim3(KV2W / 128, ROWS / 128), 256, GS_TOTAL>>>(
        ckvnh, wkb, nullptr, nullptr, khi, vhi, KV2W, KVLR, fcos, fsin);
    fill_kpe_kernel<<<ROWS, 256>>>(fcos, fsin);

    // attention (tensor-core flash, occ 3)
    flash_mma<<<dim3(SEQ / 64, NH, BSZ), 128, F_TOTAL>>>(qh, khi, vhi);

    // output projection
    gemm_mma<0><<<dim3(DIM / 128, ROWS / 128), 256, GS_TOTAL>>>(
        ath, wo16, out, nullptr, nullptr, nullptr, DIM, OW, fcos, fsin);
}

// round 14
// speedup vs baseline: 1.1713x; 1.1541x over previous
#include <cuda_runtime.h>
#include <cuda_fp16.h>
#include <cstdint>
#include <math.h>

// Problem constants
#define BSZ   2
#define SEQ   2048
#define DIM   2048
#define NH    16
#define DRr   64
#define DNn   64
#define DQK   128
#define DVv   128
#define QLR   1536
#define KVLR  1024
#define ROWS  (BSZ*SEQ)          // 4096
#define KVAW  (KVLR + DRr)       // 1088
#define KV2W  (NH*(DNn+DVv))     // 3072
#define QW    (NH*DQK)           // 2048
#define OW    (NH*DVv)           // 2048

// -------- fp32 scratch --------
__device__ float g_qa  [ (size_t)ROWS * QLR  ];
__device__ float g_kv  [ (size_t)ROWS * KVAW ];

// -------- fp16 operands --------
__device__ __half g_xh   [(size_t)ROWS*DIM];
__device__ __half g_wqa  [(size_t)QLR*DIM];
__device__ __half g_wqb  [(size_t)QW*QLR];
__device__ __half g_wkva [(size_t)KVAW*DIM];
__device__ __half g_wkvb [(size_t)KV2W*KVLR];
__device__ __half g_wo16 [(size_t)DIM*OW];
__device__ __half g_qanh [(size_t)ROWS*QLR];
__device__ __half g_ckvnh[(size_t)ROWS*KVLR];
__device__ __half g_ath  [(size_t)ROWS*OW];
__device__ __half g_qh   [(size_t)ROWS*QW];
__device__ __half g_khi  [(size_t)ROWS*QW];
__device__ __half g_vhi  [(size_t)ROWS*OW];

// ============================================================
// helpers (sm_80-compatible instructions only — plain sm_103 target!)
// ============================================================
__device__ __forceinline__ uint32_t smem_u32(const void* p) {
    uint32_t a;
    asm("{ .reg .u64 t; cvta.to.shared.u64 t, %1; cvt.u32.u64 %0, t; }" : "=r"(a) : "l"(p));
    return a;
}

#define CP16(dst, src) \
    asm volatile("cp.async.cg.shared.global [%0], [%1], 16;" :: "r"(dst), "l"(src))
#define CP_COMMIT() asm volatile("cp.async.commit_group;" ::: "memory")
#define CP_WAIT(n)  asm volatile("cp.async.wait_group %0;" :: "n"(n) : "memory")

#define LDSM4(r0, r1, r2, r3, addr) \
    asm volatile("ldmatrix.sync.aligned.m8n8.x4.shared.b16 {%0,%1,%2,%3}, [%4];" \
        : "=r"(r0), "=r"(r1), "=r"(r2), "=r"(r3) : "r"(addr))

#define LDSM4T(r0, r1, r2, r3, addr) \
    asm volatile("ldmatrix.sync.aligned.m8n8.x4.trans.shared.b16 {%0,%1,%2,%3}, [%4];" \
        : "=r"(r0), "=r"(r1), "=r"(r2), "=r"(r3) : "r"(addr))

#define MMA_F16(d, a, b0, b1) \
    asm volatile("mma.sync.aligned.m16n8k16.row.col.f32.f16.f16.f32 " \
        "{%0,%1,%2,%3},{%4,%5,%6,%7},{%8,%9},{%0,%1,%2,%3};" \
        : "+f"((d)[0]), "+f"((d)[1]), "+f"((d)[2]), "+f"((d)[3]) \
        : "r"((a)[0]), "r"((a)[1]), "r"((a)[2]), "r"((a)[3]), "r"(b0), "r"(b1))

// ============================================================
// elementwise kernels (vectorized: 4 elems/thread)
// ============================================================
__global__ void conv_h4_kernel(const float4* __restrict__ in, uint2* __restrict__ out, int n4)
{
    int i = blockIdx.x * blockDim.x + threadIdx.x;
    if (i < n4) {
        float4 v = in[i];
        __half2 h0 = __floats2half2_rn(v.x, v.y);
        __half2 h1 = __floats2half2_rn(v.z, v.w);
        out[i] = make_uint2(*(uint32_t*)&h0, *(uint32_t*)&h1);
    }
}

// RMSNorm: fp32 in (strided) -> fp16 out, vectorized
__global__ void rmsnorm_h_kernel(const float* __restrict__ in, const float* __restrict__ w,
                                 __half* __restrict__ out, int K, int inStride)
{
    const int row = blockIdx.x;
    const float4* ip4 = (const float4*)(in + (size_t)row * inStride);
    const float4* w4  = (const float4*)w;
    uint2* op4 = (uint2*)(out + (size_t)row * K);
    const int K4 = K >> 2;

    float ss = 0.f;
    for (int i = threadIdx.x; i < K4; i += blockDim.x) {
        float4 v = ip4[i];
        ss += v.x * v.x + v.y * v.y + v.z * v.z + v.w * v.w;
    }
#pragma unroll
    for (int o = 16; o; o >>= 1) ss += __shfl_xor_sync(0xffffffffu, ss, o);

    __shared__ float red[8];
    __shared__ float rs;
    int wid = threadIdx.x >> 5, lid = threadIdx.x & 31;
    if (lid == 0) red[wid] = ss;
    __syncthreads();
    if (threadIdx.x == 0) {
        float t = 0.f;
        for (int i = 0; i < 8; i++) t += red[i];
        rs = rsqrtf(t / (float)K + 1e-6f);
    }
    __syncthreads();
    float r = rs;
    for (int i = threadIdx.x; i < K4; i += blockDim.x) {
        float4 v = ip4[i];
        float4 ww = w4[i];
        __half2 h0 = __floats2half2_rn(v.x * r * ww.x, v.y * r * ww.y);
        __half2 h1 = __floats2half2_rn(v.z * r * ww.z, v.w * r * ww.w);
        op4[i] = make_uint2(*(uint32_t*)&h0, *(uint32_t*)&h1);
    }
}

// Fill rotated k_pe into g_khi cols [h*128+64, h*128+128) for all heads.
__global__ void fill_kpe_kernel(const float* __restrict__ fcos, const float* __restrict__ fsin)
{
    const int row = blockIdx.x;
    const int tid = threadIdx.x;        // 256
    __shared__ float pe[64];
    const int s = row & (SEQ - 1);
    if (tid < 32) {
        float x0 = g_kv[(size_t)row * KVAW + KVLR + 2 * tid];
        float x1 = g_kv[(size_t)row * KVAW + KVLR + 2 * tid + 1];
        float c = fcos[s * 32 + tid], sn = fsin[s * 32 + tid];
        pe[2 * tid]     = x0 * c - x1 * sn;
        pe[2 * tid + 1] = x0 * sn + x1 * c;
    }
    __syncthreads();
#pragma unroll
    for (int l = 0; l < 2; l++) {
        int idx = tid + l * 256;        // 0..511: h = idx>>5, pair = idx&31
        int h = idx >> 5, pr = idx & 31;
        *(__half2*)&g_khi[(size_t)row * QW + h * DQK + DNn + 2 * pr] =
            __floats2half2_rn(pe[2 * pr], pe[2 * pr + 1]);
    }
}

// ============================================================
// single-term fp16 GEMM via mma.sync: C = A[M,K] @ W[N,K]^T
// 128x128x32 tiles, 3-stage cp.async pipeline, 8 warps (4m x 2n), occ 2.
// (R11 configuration — BK=32; BK=64 regressed in R13.)
// EPI = 0: fp32 C row-major (bounds-checked)
// EPI = 1: fused RoPE on d>=64 of each 128-head-slice + fp16 -> Hq (N=2048)
// EPI = 2: fused scatter of kv2 cols -> Hk (k_nope) / Hv (v), fp16 (N=3072)
// ============================================================
#define GBM 128
#define GBN 128
#define ROWB 80
#define MAT_BYTES (128 * ROWB)         // 10240
#define OFF_A   0
#define OFF_W   (1 * MAT_BYTES)
#define STAGE_BYTES (2 * MAT_BYTES)    // 20480
#define NSTAGE 3
#define GS_TOTAL (NSTAGE * STAGE_BYTES) // 61440

template<int EPI>
__global__ void __launch_bounds__(256, 2)
gemm_mma(const __half* __restrict__ A, const __half* __restrict__ W,
         float* __restrict__ C, __half* __restrict__ Hq,
         __half* __restrict__ Hk, __half* __restrict__ Hv,
         int N, int K,
         const float* __restrict__ fcos, const float* __restrict__ fsin)
{
    extern __shared__ char smx[];
    const uint32_t sb = smem_u32(smx);
    const int tid  = threadIdx.x;
    const int lane = tid & 31;
    const int warp = tid >> 5;
    const int wm = warp >> 1, wn = warp & 1;
    const int m0 = blockIdx.y * GBM;
    const int n0 = blockIdx.x * GBN;

    const int lrow = tid & 127;
    const int lc   = tid >> 7;
    const size_t a_g = (size_t)(m0 + lrow) * K;
    int wr = n0 + lrow; if (wr >= N) wr = N - 1;
    const size_t w_g = (size_t)wr * K;
    const uint32_t s_row = (uint32_t)lrow * ROWB;

    const uint32_t a_lm = (uint32_t)(wm * 32 + (lane & 15)) * ROWB + (uint32_t)(lane >> 4) * 16;
    const uint32_t b_lm = (uint32_t)(wn * 64 + (lane & 7) + ((lane >> 4) << 3)) * ROWB
                        + (uint32_t)((lane >> 3) & 1) * 16;

    float acc[2][8][4];
#pragma unroll
    for (int i = 0; i < 2; i++)
#pragma unroll
        for (int j = 0; j < 8; j++)
#pragma unroll
            for (int q = 0; q < 4; q++) acc[i][j][q] = 0.f;

    const int nch = K >> 5;

    // prologue: chunks 0,1 into stages 0,1
#pragma unroll
    for (int p = 0; p < NSTAGE - 1; p++) {
        const int k0 = p << 5;
        const uint32_t st = sb + p * STAGE_BYTES + s_row;
#pragma unroll
        for (int u = 0; u < 2; u++) {
            const int cc = lc + u * 2;
            CP16(st + OFF_A + cc * 16, A + a_g + k0 + cc * 8);
            CP16(st + OFF_W + cc * 16, W + w_g + k0 + cc * 8);
        }
        CP_COMMIT();
    }

    int stage = 0;
    for (int c = 0; c < nch; c++) {
        CP_WAIT(NSTAGE - 2);
        __syncthreads();

        if (c + NSTAGE - 1 < nch) {
            const int k0 = (c + NSTAGE - 1) << 5;
            int ws = stage + NSTAGE - 1; if (ws >= NSTAGE) ws -= NSTAGE;
            const uint32_t st = sb + ws * STAGE_BYTES + s_row;
#pragma unroll
            for (int u = 0; u < 2; u++) {
                const int cc = lc + u * 2;
                CP16(st + OFF_A + cc * 16, A + a_g + k0 + cc * 8);
                CP16(st + OFF_W + cc * 16, W + w_g + k0 + cc * 8);
            }
        }
        CP_COMMIT();

        const uint32_t base = sb + stage * STAGE_BYTES;
#pragma unroll
        for (int kk = 0; kk < 2; kk++) {
            uint32_t a[2][4], bh[4][4];
#pragma unroll
            for (int i = 0; i < 2; i++) {
                const uint32_t ao = base + OFF_A + a_lm + i * (16 * ROWB) + kk * 32;
                LDSM4(a[i][0], a[i][1], a[i][2], a[i][3], ao);
            }
#pragma unroll
            for (int g = 0; g < 4; g++) {
                const uint32_t bo = base + OFF_W + b_lm + g * (16 * ROWB) + kk * 32;
                LDSM4(bh[g][0], bh[g][1], bh[g][2], bh[g][3], bo);
            }
#pragma unroll
            for (int i = 0; i < 2; i++) {
#pragma unroll
                for (int j = 0; j < 8; j++) {
                    const int g = j >> 1, h = (j & 1) * 2;
                    MMA_F16(acc[i][j], a[i], bh[g][h], bh[g][h + 1]);
                }
            }
        }
        if (++stage == NSTAGE) stage = 0;
    }

    // ---- epilogue ----
#pragma unroll
    for (int i = 0; i < 2; i++) {
        const int row  = m0 + wm * 32 + i * 16 + (lane >> 2);
        const int row2 = row + 8;
#pragma unroll
        for (int j = 0; j < 8; j++) {
            const int col = n0 + wn * 64 + j * 8 + 2 * (lane & 3);
            float a0 = acc[i][j][0], a1 = acc[i][j][1];
            float b0 = acc[i][j][2], b1 = acc[i][j][3];

            if (EPI == 0) {
                if (col < N) {
                    *(float2*)&C[(size_t)row  * N + col] = make_float2(a0, a1);
                    *(float2*)&C[(size_t)row2 * N + col] = make_float2(b0, b1);
                }
            } else if (EPI == 1) {
                const int d = col & 127;
                if (d >= DNn) {
                    const int ir = (d - DNn) >> 1;
                    const int s0 = row & (SEQ - 1), s1 = row2 & (SEQ - 1);
                    float c0 = fcos[s0 * 32 + ir], sn0 = fsin[s0 * 32 + ir];
                    float c1 = fcos[s1 * 32 + ir], sn1 = fsin[s1 * 32 + ir];
                    float t0 = a0 * c0 - a1 * sn0, t1 = a0 * sn0 + a1 * c0;
                    a0 = t0; a1 = t1;
                    t0 = b0 * c1 - b1 * sn1; t1 = b0 * sn1 + b1 * c1;
                    b0 = t0; b1 = t1;
                }
                *(__half2*)&Hq[(size_t)row  * QW + col] = __floats2half2_rn(a0, a1);
                *(__half2*)&Hq[(size_t)row2 * QW + col] = __floats2half2_rn(b0, b1);
            } else {
                const int h = col / (DNn + DVv);
                const int d = col - h * (DNn + DVv);
                if (d < DNn) {
                    const size_t off = (size_t)h * DQK + d;
                    *(__half2*)&Hk[(size_t)row  * QW + off] = __floats2half2_rn(a0, a1);
                    *(__half2*)&Hk[(size_t)row2 * QW + off] = __floats2half2_rn(b0, b1);
                } else {
                    const size_t off = (size_t)h * DVv + (d - DNn);
                    *(__half2*)&Hv[(size_t)row  * OW + off] = __floats2half2_rn(a0, a1);
                    *(__half2*)&Hv[(size_t)row2 * OW + off] = __floats2half2_rn(b0, b1);
                }
            }
        }
    }
}

// ============================================================
// Flash attention — FA2-style, fp16 mma.sync, occupancy 3
// BQ=64, BK=64, 4 warps (each owns 16 rows), block 128.
// Q fragments in registers; K + V in 2-stage cp.async ring; prefetch of
// tile kt+2 into the CURRENT stage strictly after the post-compute sync.
// grid: (SEQ/64, NH, BSZ)
// ============================================================
#define RB 272
#define SK    0
#define SV    17408
#define FSTG  34816                   // per stage: K + V
#define F_TOTAL (2 * FSTG)            // 69632

__global__ void __launch_bounds__(128, 3)
flash_mma(const __half* __restrict__ q16,
          const __half* __restrict__ khi, const __half* __restrict__ vhi)
{
    extern __shared__ char smx[];
    const uint32_t sb = smem_u32(smx);
    const int tid = threadIdx.x, lane = tid & 31, wid = tid >> 5;   // 4 warps
    const int q0 = blockIdx.x * 64;
    const int h  = blockIdx.y;
    const int b  = blockIdx.z;
    const float scale = 0.088388347648318447f;  // 128^-0.5

    const uint32_t a_off  = (uint32_t)(wid * 16 + (lane & 15)) * RB + (uint32_t)(lane >> 4) * 16;
    const uint32_t bK_off = (uint32_t)((lane & 7) + ((lane >> 4) << 3)) * RB
                          + (uint32_t)((lane >> 3) & 1) * 16;
    const uint32_t bV_off = (uint32_t)((lane & 7) + (((lane >> 3) & 1) << 3)) * RB
                          + (uint32_t)(lane >> 4) * 16;

    // ---- stage Q tile (64 x 128) through smem stage-0, hoist fragments
    {
        int r = tid >> 4;
        const int cc = tid & 15;
#pragma unroll
        for (int it = 0; it < 8; it++, r += 8) {
            size_t go = (size_t)(b * SEQ + q0 + r) * QW + h * DQK + cc * 8;
            *(uint4*)(smx + (uint32_t)r * RB + cc * 16) = *(const uint4*)(q16 + go);
        }
    }
    __syncthreads();
    uint32_t aq[8][4];
#pragma unroll
    for (int kk = 0; kk < 8; kk++)
        LDSM4(aq[kk][0], aq[kk][1], aq[kk][2], aq[kk][3], sb + a_off + kk * 32);
    __syncthreads();

    float oacc[16][4];
#pragma unroll
    for (int t = 0; t < 16; t++)
#pragma unroll
        for (int qq = 0; qq < 4; qq++) oacc[t][qq] = 0.f;
    float m0 = -1e30f, m1 = -1e30f, l0 = 0.f, l1 = 0.f;

    const int row0 = q0 + wid * 16 + (lane >> 2);
    const int row1 = row0 + 8;

    const int nkt = blockIdx.x + 1;
    const int ldr_r0 = tid >> 4;        // 8 rows per pass, 8 passes
    const int ldr_c  = tid & 15;

    // prologue: tiles 0,1 into stages 0,1 (empty commit when nkt==1)
#pragma unroll
    for (int p = 0; p < 2; p++) {
        if (p < nkt) {
            const uint32_t stg = sb + p * FSTG;
            int r = ldr_r0;
#pragma unroll
            for (int it = 0; it < 8; it++, r += 8) {
                size_t grow = (size_t)(b * SEQ + p * 64 + r);
                size_t gk = grow * QW + h * DQK + ldr_c * 8;
                size_t gv = grow * OW + h * DVv + ldr_c * 8;
                uint32_t so = (uint32_t)r * RB + ldr_c * 16;
                CP16(stg + SK + so, khi + gk);
                CP16(stg + SV + so, vhi + gv);
            }
        }
        CP_COMMIT();
    }

    int stage = 0;
    for (int kt = 0; kt < nkt; kt++) {
        const int t0 = kt * 64;
        CP_WAIT(1);                    // tile kt resident
        __syncthreads();               // make it visible to all warps

        const uint32_t stg = sb + stage * FSTG;

        // ---- S = Q @ K^T  (warp tile 16 x 64)
        float sacc[8][4];
#pragma unroll
        for (int t = 0; t < 8; t++)
#pragma unroll
            for (int qq = 0; qq < 4; qq++) sacc[t][qq] = 0.f;

#pragma unroll
        for (int kk = 0; kk < 8; kk++) {
#pragma unroll
            for (int g = 0; g < 4; g++) {
                uint32_t bh[4];
                const uint32_t bo = bK_off + g * (16 * RB) + kk * 32;
                LDSM4(bh[0], bh[1], bh[2], bh[3], stg + SK + bo);
                MMA_F16(sacc[2*g],   aq[kk], bh[0], bh[1]);
                MMA_F16(sacc[2*g+1], aq[kk], bh[2], bh[3]);
            }
        }

        // ---- scale + causal mask
        const int cb = t0 + 2 * (lane & 3);
#pragma unroll
        for (int t = 0; t < 8; t++) {
            const int c0 = cb + 8 * t, c1 = c0 + 1;
            sacc[t][0] = sacc[t][0] * scale + ((c0 > row0) ? -1e9f : 0.f);
            sacc[t][1] = sacc[t][1] * scale + ((c1 > row0) ? -1e9f : 0.f);
            sacc[t][2] = sacc[t][2] * scale + ((c0 > row1) ? -1e9f : 0.f);
            sacc[t][3] = sacc[t][3] * scale + ((c1 > row1) ? -1e9f : 0.f);
        }

        // ---- online softmax
        float mx0 = -1e30f, mx1 = -1e30f;
#pragma unroll
        for (int t = 0; t < 8; t++) {
            mx0 = fmaxf(mx0, fmaxf(sacc[t][0], sacc[t][1]));
            mx1 = fmaxf(mx1, fmaxf(sacc[t][2], sacc[t][3]));
        }
        mx0 = fmaxf(mx0, __shfl_xor_sync(0xffffffffu, mx0, 1));
        mx0 = fmaxf(mx0, __shfl_xor_sync(0xffffffffu, mx0, 2));
        mx1 = fmaxf(mx1, __shfl_xor_sync(0xffffffffu, mx1, 1));
        mx1 = fmaxf(mx1, __shfl_xor_sync(0xffffffffu, mx1, 2));

        const float mn0 = fmaxf(m0, mx0), mn1 = fmaxf(m1, mx1);
        const float al0 = __expf(m0 - mn0), al1 = __expf(m1 - mn1);
        m0 = mn0; m1 = mn1;

        float ps0 = 0.f, ps1 = 0.f;
#pragma unroll
        for (int t = 0; t < 8; t++) {
            sacc[t][0] = __expf(sacc[t][0] - mn0);
            sacc[t][1] = __expf(sacc[t][1] - mn0);
            sacc[t][2] = __expf(sacc[t][2] - mn1);
            sacc[t][3] = __expf(sacc[t][3] - mn1);
            ps0 += sacc[t][0] + sacc[t][1];
            ps1 += sacc[t][2] + sacc[t][3];
        }
        ps0 += __shfl_xor_sync(0xffffffffu, ps0, 1);
        ps0 += __shfl_xor_sync(0xffffffffu, ps0, 2);
        ps1 += __shfl_xor_sync(0xffffffffu, ps1, 1);
        ps1 += __shfl_xor_sync(0xffffffffu, ps1, 2);
        l0 = l0 * al0 + ps0;
        l1 = l1 * al1 + ps1;

#pragma unroll
        for (int t = 0; t < 16; t++) {
            oacc[t][0] *= al0; oacc[t][1] *= al0;
            oacc[t][2] *= al1; oacc[t][3] *= al1;
        }

        // ---- O += P @ V
#pragma unroll
        for (int jj = 0; jj < 4; jj++) {
            const int t2 = 2 * jj, t3 = 2 * jj + 1;
            uint32_t phi[4];
            {
                __half2 h0 = __floats2half2_rn(sacc[t2][0], sacc[t2][1]);
                __half2 h1 = __floats2half2_rn(sacc[t2][2], sacc[t2][3]);
                __half2 h2 = __floats2half2_rn(sacc[t3][0], sacc[t3][1]);
                __half2 h3 = __floats2half2_rn(sacc[t3][2], sacc[t3][3]);
                phi[0] = *(uint32_t*)&h0; phi[1] = *(uint32_t*)&h1;
                phi[2] = *(uint32_t*)&h2; phi[3] = *(uint32_t*)&h3;
            }
#pragma unroll
            for (int g = 0; g < 8; g++) {
                uint32_t bv[4];
                const uint32_t bo = bV_off + jj * (16 * RB) + g * 32;
                LDSM4T(bv[0], bv[1], bv[2], bv[3], stg + SV + bo);
                MMA_F16(oacc[2*g],   phi, bv[0], bv[1]);
                MMA_F16(oacc[2*g+1], phi, bv[2], bv[3]);
            }
        }

        // ---- stage fully consumed by ALL warps: now prefetch tile kt+2 into it
        __syncthreads();
        if (kt + 2 < nkt) {
            int r = ldr_r0;
#pragma unroll
            for (int it = 0; it < 8; it++, r += 8) {
                size_t grow = (size_t)(b * SEQ + (kt + 2) * 64 + r);
                size_t gk = grow * QW + h * DQK + ldr_c * 8;
                size_t gv = grow * OW + h * DVv + ldr_c * 8;
                uint32_t so = stg + (uint32_t)r * RB + ldr_c * 16;
                CP16(so + SK, khi + gk);
                CP16(so + SV, vhi + gv);
            }
        }
        CP_COMMIT();
        stage ^= 1;
    }

    // ---- epilogue: write fp16 attn directly (A operand of final GEMM)
    const float inv0 = 1.f / l0, inv1 = 1.f / l1;
    const size_t o0 = (size_t)(b * SEQ + row0) * OW + h * DVv;
    const size_t o1 = (size_t)(b * SEQ + row1) * OW + h * DVv;
#pragma unroll
    for (int t = 0; t < 16; t++) {
        const int d0 = 8 * t + 2 * (lane & 3);
        __half2 v0 = __floats2half2_rn(oacc[t][0] * inv0, oacc[t][1] * inv0);
        __half2 v1 = __floats2half2_rn(oacc[t][2] * inv1, oacc[t][3] * inv1);
        *(__half2*)&g_ath[o0 + d0] = v0;
        *(__half2*)&g_ath[o1 + d0] = v1;
    }
}

// ============================================================
// launch — q-chain and kv-chain forked onto two streams (graph-capture
// fork/join via events), joined before flash.
// ============================================================
static inline void convw_s(cudaStream_t s, const float* in, __half* out, size_t n)
{
    conv_h4_kernel<<<(int)((n / 4 + 255) / 256), 256, 0, s>>>(
        (const float4*)in, (uint2*)out, (int)(n / 4));
}

extern "C" void kernel_launch(void* const* d_in, const int* in_sizes, int n_in,
                              void* d_out, int out_size)
{
    const float* x      = (const float*)d_in[0];
    const float* wq_a   = (const float*)d_in[1];
    const float* qnw    = (const float*)d_in[2];
    const float* wq_b   = (const float*)d_in[3];
    const float* wkv_a  = (const float*)d_in[4];
    const float* kvnw   = (const float*)d_in[5];
    const float* wkv_b  = (const float*)d_in[6];
    const float* wo     = (const float*)d_in[7];
    const float* fcos   = (const float*)d_in[9];
    const float* fsin   = (const float*)d_in[10];

    float* out = (float*)d_out;

    float *p_qa, *p_kv;
    cudaGetSymbolAddress((void**)&p_qa,   g_qa);
    cudaGetSymbolAddress((void**)&p_kv,   g_kv);

    __half *xh, *wqa, *wqb, *wka, *wkb, *wo16, *qanh, *ckvnh, *ath, *qh, *khi, *vhi;
    cudaGetSymbolAddress((void**)&xh,   g_xh);
    cudaGetSymbolAddress((void**)&wqa,  g_wqa);
    cudaGetSymbolAddress((void**)&wqb,  g_wqb);
    cudaGetSymbolAddress((void**)&wka,  g_wkva);
    cudaGetSymbolAddress((void**)&wkb,  g_wkvb);
    cudaGetSymbolAddress((void**)&wo16, g_wo16);
    cudaGetSymbolAddress((void**)&qanh, g_qanh);
    cudaGetSymbolAddress((void**)&ckvnh,g_ckvnh);
    cudaGetSymbolAddress((void**)&ath,  g_ath);
    cudaGetSymbolAddress((void**)&qh,   g_qh);
    cudaGetSymbolAddress((void**)&khi,  g_khi);
    cudaGetSymbolAddress((void**)&vhi,  g_vhi);

    cudaFuncSetAttribute(gemm_mma<0>, cudaFuncAttributeMaxDynamicSharedMemorySize, GS_TOTAL);
    cudaFuncSetAttribute(gemm_mma<1>, cudaFuncAttributeMaxDynamicSharedMemorySize, GS_TOTAL);
    cudaFuncSetAttribute(gemm_mma<2>, cudaFuncAttributeMaxDynamicSharedMemorySize, GS_TOTAL);
    cudaFuncSetAttribute(flash_mma,   cudaFuncAttributeMaxDynamicSharedMemorySize, F_TOTAL);

    // one-time host objects (no device memory involved)
    static cudaStream_t s_kv = nullptr;
    static cudaEvent_t  evFork = nullptr, evJoin = nullptr;
    if (s_kv == nullptr) {
        cudaStreamCreateWithFlags(&s_kv, cudaStreamNonBlocking);
        cudaEventCreateWithFlags(&evFork, cudaEventDisableTiming);
        cudaEventCreateWithFlags(&evJoin, cudaEventDisableTiming);
    }
    const cudaStream_t s0 = 0;   // captured (legacy default) stream

    // x must precede both chains
    convw_s(s0, x, xh, (size_t)ROWS * DIM);

    // ---- fork: kv chain on s_kv
    cudaEventRecord(evFork, s0);
    cudaStreamWaitEvent(s_kv, evFork, 0);

    // kv chain (s_kv)
    convw_s(s_kv, wkv_a, wka, (size_t)KVAW * DIM);
    convw_s(s_kv, wkv_b, wkb, (size_t)KV2W * KVLR);
    gemm_mma<0><<<dim3((KVAW + 127) / 128, ROWS / 128), 256, GS_TOTAL, s_kv>>>(
        xh, wka, p_kv, nullptr, nullptr, nullptr, KVAW, DIM, fcos, fsin);
    rmsnorm_h_kernel<<<ROWS, 256, 0, s_kv>>>(p_kv, kvnw, ckvnh, KVLR, KVAW);
    gemm_mma<2><<<dim3(KV2W / 128, ROWS / 128), 256, GS_TOTAL, s_kv>>>(
        ckvnh, wkb, nullptr, nullptr, khi, vhi, KV2W, KVLR, fcos, fsin);
    fill_kpe_kernel<<<ROWS, 256, 0, s_kv>>>(fcos, fsin);

    // q chain (s0)
    convw_s(s0, wq_a, wqa, (size_t)QLR * DIM);
    convw_s(s0, wq_b, wqb, (size_t)QW * QLR);
    convw_s(s0, wo,   wo16,(size_t)DIM * OW);
    gemm_mma<0><<<dim3(QLR / 128, ROWS / 128), 256, GS_TOTAL, s0>>>(
        xh, wqa, p_qa, nullptr, nullptr, nullptr, QLR, DIM, fcos, fsin);
    rmsnorm_h_kernel<<<ROWS, 256, 0, s0>>>(p_qa, qnw, qanh, QLR, QLR);
    gemm_mma<1><<<dim3(QW / 128, ROWS / 128), 256, GS_TOTAL, s0>>>(
        qanh, wqb, nullptr, qh, nullptr, nullptr, QW, QLR, fcos, fsin);

    // ---- join: flash needs both chains
    cudaEventRecord(evJoin, s_kv);
    cudaStreamWaitEvent(s0, evJoin, 0);

    // attention (tensor-core flash, occ 3)
    flash_mma<<<dim3(SEQ / 64, NH, BSZ), 128, F_TOTAL, s0>>>(qh, khi, vhi);

    // output projection
    gemm_mma<0><<<dim3(DIM / 128, ROWS / 128), 256, GS_TOTAL, s0>>>(
        ath, wo16, out, nullptr, nullptr, nullptr, DIM, OW, fcos, fsin);
}

// round 15
// speedup vs baseline: 1.1792x; 1.0068x over previous
#include <cuda_runtime.h>
#include <cuda_fp16.h>
#include <cstdint>
#include <math.h>

// Problem constants
#define BSZ   2
#define SEQ   2048
#define DIM   2048
#define NH    16
#define DRr   64
#define DNn   64
#define DQK   128
#define DVv   128
#define QLR   1536
#define KVLR  1024
#define ROWS  (BSZ*SEQ)          // 4096
#define KVAW  (KVLR + DRr)       // 1088
#define KV2W  (NH*(DNn+DVv))     // 3072
#define QW    (NH*DQK)           // 2048
#define OW    (NH*DVv)           // 2048

// -------- fp32 scratch --------
__device__ float g_qa  [ (size_t)ROWS * QLR  ];
__device__ float g_kv  [ (size_t)ROWS * KVAW ];

// -------- fp16 operands --------
__device__ __half g_xh   [(size_t)ROWS*DIM];
__device__ __half g_wqa  [(size_t)QLR*DIM];
__device__ __half g_wqb  [(size_t)QW*QLR];
__device__ __half g_wkva [(size_t)KVAW*DIM];
__device__ __half g_wkvb [(size_t)KV2W*KVLR];
__device__ __half g_wo16 [(size_t)DIM*OW];
__device__ __half g_qanh [(size_t)ROWS*QLR];
__device__ __half g_ckvnh[(size_t)ROWS*KVLR];
__device__ __half g_ath  [(size_t)ROWS*OW];
__device__ __half g_qh   [(size_t)ROWS*QW];
__device__ __half g_khi  [(size_t)ROWS*QW];
__device__ __half g_vhi  [(size_t)ROWS*OW];

// ============================================================
// helpers (sm_80-compatible instructions only — plain sm_103 target!)
// ============================================================
__device__ __forceinline__ uint32_t smem_u32(const void* p) {
    uint32_t a;
    asm("{ .reg .u64 t; cvta.to.shared.u64 t, %1; cvt.u32.u64 %0, t; }" : "=r"(a) : "l"(p));
    return a;
}

#define CP16(dst, src) \
    asm volatile("cp.async.cg.shared.global [%0], [%1], 16;" :: "r"(dst), "l"(src))
#define CP_COMMIT() asm volatile("cp.async.commit_group;" ::: "memory")
#define CP_WAIT(n)  asm volatile("cp.async.wait_group %0;" :: "n"(n) : "memory")

#define LDSM4(r0, r1, r2, r3, addr) \
    asm volatile("ldmatrix.sync.aligned.m8n8.x4.shared.b16 {%0,%1,%2,%3}, [%4];" \
        : "=r"(r0), "=r"(r1), "=r"(r2), "=r"(r3) : "r"(addr))

#define LDSM4T(r0, r1, r2, r3, addr) \
    asm volatile("ldmatrix.sync.aligned.m8n8.x4.trans.shared.b16 {%0,%1,%2,%3}, [%4];" \
        : "=r"(r0), "=r"(r1), "=r"(r2), "=r"(r3) : "r"(addr))

#define MMA_F16(d, a, b0, b1) \
    asm volatile("mma.sync.aligned.m16n8k16.row.col.f32.f16.f16.f32 " \
        "{%0,%1,%2,%3},{%4,%5,%6,%7},{%8,%9},{%0,%1,%2,%3};" \
        : "+f"((d)[0]), "+f"((d)[1]), "+f"((d)[2]), "+f"((d)[3]) \
        : "r"((a)[0]), "r"((a)[1]), "r"((a)[2]), "r"((a)[3]), "r"(b0), "r"(b1))

// ============================================================
// elementwise kernels (vectorized: 4 elems/thread)
// ============================================================
__global__ void conv_h4_kernel(const float4* __restrict__ in, uint2* __restrict__ out, int n4)
{
    int i = blockIdx.x * blockDim.x + threadIdx.x;
    if (i < n4) {
        float4 v = in[i];
        __half2 h0 = __floats2half2_rn(v.x, v.y);
        __half2 h1 = __floats2half2_rn(v.z, v.w);
        out[i] = make_uint2(*(uint32_t*)&h0, *(uint32_t*)&h1);
    }
}

// RMSNorm: fp32 in (strided) -> fp16 out, vectorized
__global__ void rmsnorm_h_kernel(const float* __restrict__ in, const float* __restrict__ w,
                                 __half* __restrict__ out, int K, int inStride)
{
    const int row = blockIdx.x;
    const float4* ip4 = (const float4*)(in + (size_t)row * inStride);
    const float4* w4  = (const float4*)w;
    uint2* op4 = (uint2*)(out + (size_t)row * K);
    const int K4 = K >> 2;

    float ss = 0.f;
    for (int i = threadIdx.x; i < K4; i += blockDim.x) {
        float4 v = ip4[i];
        ss += v.x * v.x + v.y * v.y + v.z * v.z + v.w * v.w;
    }
#pragma unroll
    for (int o = 16; o; o >>= 1) ss += __shfl_xor_sync(0xffffffffu, ss, o);

    __shared__ float red[8];
    __shared__ float rs;
    int wid = threadIdx.x >> 5, lid = threadIdx.x & 31;
    if (lid == 0) red[wid] = ss;
    __syncthreads();
    if (threadIdx.x == 0) {
        float t = 0.f;
        for (int i = 0; i < 8; i++) t += red[i];
        rs = rsqrtf(t / (float)K + 1e-6f);
    }
    __syncthreads();
    float r = rs;
    for (int i = threadIdx.x; i < K4; i += blockDim.x) {
        float4 v = ip4[i];
        float4 ww = w4[i];
        __half2 h0 = __floats2half2_rn(v.x * r * ww.x, v.y * r * ww.y);
        __half2 h1 = __floats2half2_rn(v.z * r * ww.z, v.w * r * ww.w);
        op4[i] = make_uint2(*(uint32_t*)&h0, *(uint32_t*)&h1);
    }
}

// Fill rotated k_pe into g_khi cols [h*128+64, h*128+128) for all heads.
__global__ void fill_kpe_kernel(const float* __restrict__ fcos, const float* __restrict__ fsin)
{
    const int row = blockIdx.x;
    const int tid = threadIdx.x;        // 256
    __shared__ float pe[64];
    const int s = row & (SEQ - 1);
    if (tid < 32) {
        float x0 = g_kv[(size_t)row * KVAW + KVLR + 2 * tid];
        float x1 = g_kv[(size_t)row * KVAW + KVLR + 2 * tid + 1];
        float c = fcos[s * 32 + tid], sn = fsin[s * 32 + tid];
        pe[2 * tid]     = x0 * c - x1 * sn;
        pe[2 * tid + 1] = x0 * sn + x1 * c;
    }
    __syncthreads();
#pragma unroll
    for (int l = 0; l < 2; l++) {
        int idx = tid + l * 256;        // 0..511: h = idx>>5, pair = idx&31
        int h = idx >> 5, pr = idx & 31;
        *(__half2*)&g_khi[(size_t)row * QW + h * DQK + DNn + 2 * pr] =
            __floats2half2_rn(pe[2 * pr], pe[2 * pr + 1]);
    }
}

// ============================================================
// single-term fp16 GEMM via mma.sync: C = A[M,K] @ W[N,K]^T
// 128x128x32 tiles, 4-stage cp.async pipeline, 8 warps (4m x 2n), occ 2.
// EPI = 0: fp32 C row-major (bounds-checked)
// EPI = 1: fused RoPE on d>=64 of each 128-head-slice + fp16 -> Hq (N=2048)
// EPI = 2: fused scatter of kv2 cols -> Hk (k_nope) / Hv (v), fp16 (N=3072)
// ============================================================
#define GBM 128
#define GBN 128
#define ROWB 80
#define MAT_BYTES (128 * ROWB)         // 10240
#define OFF_A   0
#define OFF_W   (1 * MAT_BYTES)
#define STAGE_BYTES (2 * MAT_BYTES)    // 20480
#define NSTAGE 4
#define GS_TOTAL (NSTAGE * STAGE_BYTES) // 81920

template<int EPI>
__global__ void __launch_bounds__(256, 2)
gemm_mma(const __half* __restrict__ A, const __half* __restrict__ W,
         float* __restrict__ C, __half* __restrict__ Hq,
         __half* __restrict__ Hk, __half* __restrict__ Hv,
         int N, int K,
         const float* __restrict__ fcos, const float* __restrict__ fsin)
{
    extern __shared__ char smx[];
    const uint32_t sb = smem_u32(smx);
    const int tid  = threadIdx.x;
    const int lane = tid & 31;
    const int warp = tid >> 5;
    const int wm = warp >> 1, wn = warp & 1;
    const int m0 = blockIdx.y * GBM;
    const int n0 = blockIdx.x * GBN;

    const int lrow = tid & 127;
    const int lc   = tid >> 7;
    const size_t a_g = (size_t)(m0 + lrow) * K;
    int wr = n0 + lrow; if (wr >= N) wr = N - 1;
    const size_t w_g = (size_t)wr * K;
    const uint32_t s_row = (uint32_t)lrow * ROWB;

    const uint32_t a_lm = (uint32_t)(wm * 32 + (lane & 15)) * ROWB + (uint32_t)(lane >> 4) * 16;
    const uint32_t b_lm = (uint32_t)(wn * 64 + (lane & 7) + ((lane >> 4) << 3)) * ROWB
                        + (uint32_t)((lane >> 3) & 1) * 16;

    float acc[2][8][4];
#pragma unroll
    for (int i = 0; i < 2; i++)
#pragma unroll
        for (int j = 0; j < 8; j++)
#pragma unroll
            for (int q = 0; q < 4; q++) acc[i][j][q] = 0.f;

    const int nch = K >> 5;

    // prologue: chunks 0..NSTAGE-2 into stages 0..NSTAGE-2
#pragma unroll
    for (int p = 0; p < NSTAGE - 1; p++) {
        const int k0 = p << 5;
        const uint32_t st = sb + p * STAGE_BYTES + s_row;
#pragma unroll
        for (int u = 0; u < 2; u++) {
            const int cc = lc + u * 2;
            CP16(st + OFF_A + cc * 16, A + a_g + k0 + cc * 8);
            CP16(st + OFF_W + cc * 16, W + w_g + k0 + cc * 8);
        }
        CP_COMMIT();
    }

    int stage = 0;
    for (int c = 0; c < nch; c++) {
        CP_WAIT(NSTAGE - 2);
        __syncthreads();

        if (c + NSTAGE - 1 < nch) {
            const int k0 = (c + NSTAGE - 1) << 5;
            int ws = stage + NSTAGE - 1; if (ws >= NSTAGE) ws -= NSTAGE;
            const uint32_t st = sb + ws * STAGE_BYTES + s_row;
#pragma unroll
            for (int u = 0; u < 2; u++) {
                const int cc = lc + u * 2;
                CP16(st + OFF_A + cc * 16, A + a_g + k0 + cc * 8);
                CP16(st + OFF_W + cc * 16, W + w_g + k0 + cc * 8);
            }
        }
        CP_COMMIT();

        const uint32_t base = sb + stage * STAGE_BYTES;
#pragma unroll
        for (int kk = 0; kk < 2; kk++) {
            uint32_t a[2][4], bh[4][4];
#pragma unroll
            for (int i = 0; i < 2; i++) {
                const uint32_t ao = base + OFF_A + a_lm + i * (16 * ROWB) + kk * 32;
                LDSM4(a[i][0], a[i][1], a[i][2], a[i][3], ao);
            }
#pragma unroll
            for (int g = 0; g < 4; g++) {
                const uint32_t bo = base + OFF_W + b_lm + g * (16 * ROWB) + kk * 32;
                LDSM4(bh[g][0], bh[g][1], bh[g][2], bh[g][3], bo);
            }
#pragma unroll
            for (int i = 0; i < 2; i++) {
#pragma unroll
                for (int j = 0; j < 8; j++) {
                    const int g = j >> 1, h = (j & 1) * 2;
                    MMA_F16(acc[i][j], a[i], bh[g][h], bh[g][h + 1]);
                }
            }
        }
        if (++stage == NSTAGE) stage = 0;
    }

    // ---- epilogue ----
#pragma unroll
    for (int i = 0; i < 2; i++) {
        const int row  = m0 + wm * 32 + i * 16 + (lane >> 2);
        const int row2 = row + 8;
#pragma unroll
        for (int j = 0; j < 8; j++) {
            const int col = n0 + wn * 64 + j * 8 + 2 * (lane & 3);
            float a0 = acc[i][j][0], a1 = acc[i][j][1];
            float b0 = acc[i][j][2], b1 = acc[i][j][3];

            if (EPI == 0) {
                if (col < N) {
                    *(float2*)&C[(size_t)row  * N + col] = make_float2(a0, a1);
                    *(float2*)&C[(size_t)row2 * N + col] = make_float2(b0, b1);
                }
            } else if (EPI == 1) {
                const int d = col & 127;
                if (d >= DNn) {
                    const int ir = (d - DNn) >> 1;
                    const int s0 = row & (SEQ - 1), s1 = row2 & (SEQ - 1);
                    float c0 = fcos[s0 * 32 + ir], sn0 = fsin[s0 * 32 + ir];
                    float c1 = fcos[s1 * 32 + ir], sn1 = fsin[s1 * 32 + ir];
                    float t0 = a0 * c0 - a1 * sn0, t1 = a0 * sn0 + a1 * c0;
                    a0 = t0; a1 = t1;
                    t0 = b0 * c1 - b1 * sn1; t1 = b0 * sn1 + b1 * c1;
                    b0 = t0; b1 = t1;
                }
                *(__half2*)&Hq[(size_t)row  * QW + col] = __floats2half2_rn(a0, a1);
                *(__half2*)&Hq[(size_t)row2 * QW + col] = __floats2half2_rn(b0, b1);
            } else {
                const int h = col / (DNn + DVv);
                const int d = col - h * (DNn + DVv);
                if (d < DNn) {
                    const size_t off = (size_t)h * DQK + d;
                    *(__half2*)&Hk[(size_t)row  * QW + off] = __floats2half2_rn(a0, a1);
                    *(__half2*)&Hk[(size_t)row2 * QW + off] = __floats2half2_rn(b0, b1);
                } else {
                    const size_t off = (size_t)h * DVv + (d - DNn);
                    *(__half2*)&Hv[(size_t)row  * OW + off] = __floats2half2_rn(a0, a1);
                    *(__half2*)&Hv[(size_t)row2 * OW + off] = __floats2half2_rn(b0, b1);
                }
            }
        }
    }
}

// ============================================================
// Flash attention — FA2-style, fp16 mma.sync, occupancy 3
// BQ=64, BK=64, 4 warps (each owns 16 rows), block 128.
// Q fragments in registers; K + V in 2-stage cp.async ring; prefetch of
// tile kt+2 into the CURRENT stage strictly after the post-compute sync.
// grid: (SEQ/64, NH, BSZ)
// ============================================================
#define RB 272
#define SK    0
#define SV    17408
#define FSTG  34816                   // per stage: K + V
#define F_TOTAL (2 * FSTG)            // 69632

__global__ void __launch_bounds__(128, 3)
flash_mma(const __half* __restrict__ q16,
          const __half* __restrict__ khi, const __half* __restrict__ vhi)
{
    extern __shared__ char smx[];
    const uint32_t sb = smem_u32(smx);
    const int tid = threadIdx.x, lane = tid & 31, wid = tid >> 5;   // 4 warps
    const int q0 = blockIdx.x * 64;
    const int h  = blockIdx.y;
    const int b  = blockIdx.z;
    const float scale = 0.088388347648318447f;  // 128^-0.5

    const uint32_t a_off  = (uint32_t)(wid * 16 + (lane & 15)) * RB + (uint32_t)(lane >> 4) * 16;
    const uint32_t bK_off = (uint32_t)((lane & 7) + ((lane >> 4) << 3)) * RB
                          + (uint32_t)((lane >> 3) & 1) * 16;
    const uint32_t bV_off = (uint32_t)((lane & 7) + (((lane >> 3) & 1) << 3)) * RB
                          + (uint32_t)(lane >> 4) * 16;

    // ---- stage Q tile (64 x 128) through smem stage-0, hoist fragments
    {
        int r = tid >> 4;
        const int cc = tid & 15;
#pragma unroll
        for (int it = 0; it < 8; it++, r += 8) {
            size_t go = (size_t)(b * SEQ + q0 + r) * QW + h * DQK + cc * 8;
            *(uint4*)(smx + (uint32_t)r * RB + cc * 16) = *(const uint4*)(q16 + go);
        }
    }
    __syncthreads();
    uint32_t aq[8][4];
#pragma unroll
    for (int kk = 0; kk < 8; kk++)
        LDSM4(aq[kk][0], aq[kk][1], aq[kk][2], aq[kk][3], sb + a_off + kk * 32);
    __syncthreads();

    float oacc[16][4];
#pragma unroll
    for (int t = 0; t < 16; t++)
#pragma unroll
        for (int qq = 0; qq < 4; qq++) oacc[t][qq] = 0.f;
    float m0 = -1e30f, m1 = -1e30f, l0 = 0.f, l1 = 0.f;

    const int row0 = q0 + wid * 16 + (lane >> 2);
    const int row1 = row0 + 8;

    const int nkt = blockIdx.x + 1;
    const int ldr_r0 = tid >> 4;        // 8 rows per pass, 8 passes
    const int ldr_c  = tid & 15;

    // prologue: tiles 0,1 into stages 0,1 (empty commit when nkt==1)
#pragma unroll
    for (int p = 0; p < 2; p++) {
        if (p < nkt) {
            const uint32_t stg = sb + p * FSTG;
            int r = ldr_r0;
#pragma unroll
            for (int it = 0; it < 8; it++, r += 8) {
                size_t grow = (size_t)(b * SEQ + p * 64 + r);
                size_t gk = grow * QW + h * DQK + ldr_c * 8;
                size_t gv = grow * OW + h * DVv + ldr_c * 8;
                uint32_t so = (uint32_t)r * RB + ldr_c * 16;
                CP16(stg + SK + so, khi + gk);
                CP16(stg + SV + so, vhi + gv);
            }
        }
        CP_COMMIT();
    }

    int stage = 0;
    for (int kt = 0; kt < nkt; kt++) {
        const int t0 = kt * 64;
        CP_WAIT(1);                    // tile kt resident
        __syncthreads();               // make it visible to all warps

        const uint32_t stg = sb + stage * FSTG;

        // ---- S = Q @ K^T  (warp tile 16 x 64)
        float sacc[8][4];
#pragma unroll
        for (int t = 0; t < 8; t++)
#pragma unroll
            for (int qq = 0; qq < 4; qq++) sacc[t][qq] = 0.f;

#pragma unroll
        for (int kk = 0; kk < 8; kk++) {
#pragma unroll
            for (int g = 0; g < 4; g++) {
                uint32_t bh[4];
                const uint32_t bo = bK_off + g * (16 * RB) + kk * 32;
                LDSM4(bh[0], bh[1], bh[2], bh[3], stg + SK + bo);
                MMA_F16(sacc[2*g],   aq[kk], bh[0], bh[1]);
                MMA_F16(sacc[2*g+1], aq[kk], bh[2], bh[3]);
            }
        }

        // ---- scale + causal mask
        const int cb = t0 + 2 * (lane & 3);
#pragma unroll
        for (int t = 0; t < 8; t++) {
            const int c0 = cb + 8 * t, c1 = c0 + 1;
            sacc[t][0] = sacc[t][0] * scale + ((c0 > row0) ? -1e9f : 0.f);
            sacc[t][1] = sacc[t][1] * scale + ((c1 > row0) ? -1e9f : 0.f);
            sacc[t][2] = sacc[t][2] * scale + ((c0 > row1) ? -1e9f : 0.f);
            sacc[t][3] = sacc[t][3] * scale + ((c1 > row1) ? -1e9f : 0.f);
        }

        // ---- online softmax
        float mx0 = -1e30f, mx1 = -1e30f;
#pragma unroll
        for (int t = 0; t < 8; t++) {
            mx0 = fmaxf(mx0, fmaxf(sacc[t][0], sacc[t][1]));
            mx1 = fmaxf(mx1, fmaxf(sacc[t][2], sacc[t][3]));
        }
        mx0 = fmaxf(mx0, __shfl_xor_sync(0xffffffffu, mx0, 1));
        mx0 = fmaxf(mx0, __shfl_xor_sync(0xffffffffu, mx0, 2));
        mx1 = fmaxf(mx1, __shfl_xor_sync(0xffffffffu, mx1, 1));
        mx1 = fmaxf(mx1, __shfl_xor_sync(0xffffffffu, mx1, 2));

        const float mn0 = fmaxf(m0, mx0), mn1 = fmaxf(m1, mx1);
        const float al0 = __expf(m0 - mn0), al1 = __expf(m1 - mn1);
        m0 = mn0; m1 = mn1;

        float ps0 = 0.f, ps1 = 0.f;
#pragma unroll
        for (int t = 0; t < 8; t++) {
            sacc[t][0] = __expf(sacc[t][0] - mn0);
            sacc[t][1] = __expf(sacc[t][1] - mn0);
            sacc[t][2] = __expf(sacc[t][2] - mn1);
            sacc[t][3] = __expf(sacc[t][3] - mn1);
            ps0 += sacc[t][0] + sacc[t][1];
            ps1 += sacc[t][2] + sacc[t][3];
        }
        ps0 += __shfl_xor_sync(0xffffffffu, ps0, 1);
        ps0 += __shfl_xor_sync(0xffffffffu, ps0, 2);
        ps1 += __shfl_xor_sync(0xffffffffu, ps1, 1);
        ps1 += __shfl_xor_sync(0xffffffffu, ps1, 2);
        l0 = l0 * al0 + ps0;
        l1 = l1 * al1 + ps1;

#pragma unroll
        for (int t = 0; t < 16; t++) {
            oacc[t][0] *= al0; oacc[t][1] *= al0;
            oacc[t][2] *= al1; oacc[t][3] *= al1;
        }

        // ---- O += P @ V
#pragma unroll
        for (int jj = 0; jj < 4; jj++) {
            const int t2 = 2 * jj, t3 = 2 * jj + 1;
            uint32_t phi[4];
            {
                __half2 h0 = __floats2half2_rn(sacc[t2][0], sacc[t2][1]);
                __half2 h1 = __floats2half2_rn(sacc[t2][2], sacc[t2][3]);
                __half2 h2 = __floats2half2_rn(sacc[t3][0], sacc[t3][1]);
                __half2 h3 = __floats2half2_rn(sacc[t3][2], sacc[t3][3]);
                phi[0] = *(uint32_t*)&h0; phi[1] = *(uint32_t*)&h1;
                phi[2] = *(uint32_t*)&h2; phi[3] = *(uint32_t*)&h3;
            }
#pragma unroll
            for (int g = 0; g < 8; g++) {
                uint32_t bv[4];
                const uint32_t bo = bV_off + jj * (16 * RB) + g * 32;
                LDSM4T(bv[0], bv[1], bv[2], bv[3], stg + SV + bo);
                MMA_F16(oacc[2*g],   phi, bv[0], bv[1]);
                MMA_F16(oacc[2*g+1], phi, bv[2], bv[3]);
            }
        }

        // ---- stage fully consumed by ALL warps: now prefetch tile kt+2 into it
        __syncthreads();
        if (kt + 2 < nkt) {
            int r = ldr_r0;
#pragma unroll
            for (int it = 0; it < 8; it++, r += 8) {
                size_t grow = (size_t)(b * SEQ + (kt + 2) * 64 + r);
                size_t gk = grow * QW + h * DQK + ldr_c * 8;
                size_t gv = grow * OW + h * DVv + ldr_c * 8;
                uint32_t so = stg + (uint32_t)r * RB + ldr_c * 16;
                CP16(so + SK, khi + gk);
                CP16(so + SV, vhi + gv);
            }
        }
        CP_COMMIT();
        stage ^= 1;
    }

    // ---- epilogue: write fp16 attn directly (A operand of final GEMM)
    const float inv0 = 1.f / l0, inv1 = 1.f / l1;
    const size_t o0 = (size_t)(b * SEQ + row0) * OW + h * DVv;
    const size_t o1 = (size_t)(b * SEQ + row1) * OW + h * DVv;
#pragma unroll
    for (int t = 0; t < 16; t++) {
        const int d0 = 8 * t + 2 * (lane & 3);
        __half2 v0 = __floats2half2_rn(oacc[t][0] * inv0, oacc[t][1] * inv0);
        __half2 v1 = __floats2half2_rn(oacc[t][2] * inv1, oacc[t][3] * inv1);
        *(__half2*)&g_ath[o0 + d0] = v0;
        *(__half2*)&g_ath[o1 + d0] = v1;
    }
}

// ============================================================
// launch — q-chain and kv-chain forked onto two streams (graph-capture
// fork/join via events), joined before flash.
// ============================================================
static inline void convw_s(cudaStream_t s, const float* in, __half* out, size_t n)
{
    conv_h4_kernel<<<(int)((n / 4 + 255) / 256), 256, 0, s>>>(
        (const float4*)in, (uint2*)out, (int)(n / 4));
}

extern "C" void kernel_launch(void* const* d_in, const int* in_sizes, int n_in,
                              void* d_out, int out_size)
{
    const float* x      = (const float*)d_in[0];
    const float* wq_a   = (const float*)d_in[1];
    const float* qnw    = (const float*)d_in[2];
    const float* wq_b   = (const float*)d_in[3];
    const float* wkv_a  = (const float*)d_in[4];
    const float* kvnw   = (const float*)d_in[5];
    const float* wkv_b  = (const float*)d_in[6];
    const float* wo     = (const float*)d_in[7];
    const float* fcos   = (const float*)d_in[9];
    const float* fsin   = (const float*)d_in[10];

    float* out = (float*)d_out;

    float *p_qa, *p_kv;
    cudaGetSymbolAddress((void**)&p_qa,   g_qa);
    cudaGetSymbolAddress((void**)&p_kv,   g_kv);

    __half *xh, *wqa, *wqb, *wka, *wkb, *wo16, *qanh, *ckvnh, *ath, *qh, *khi, *vhi;
    cudaGetSymbolAddress((void**)&xh,   g_xh);
    cudaGetSymbolAddress((void**)&wqa,  g_wqa);
    cudaGetSymbolAddress((void**)&wqb,  g_wqb);
    cudaGetSymbolAddress((void**)&wka,  g_wkva);
    cudaGetSymbolAddress((void**)&wkb,  g_wkvb);
    cudaGetSymbolAddress((void**)&wo16, g_wo16);
    cudaGetSymbolAddress((void**)&qanh, g_qanh);
    cudaGetSymbolAddress((void**)&ckvnh,g_ckvnh);
    cudaGetSymbolAddress((void**)&ath,  g_ath);
    cudaGetSymbolAddress((void**)&qh,   g_qh);
    cudaGetSymbolAddress((void**)&khi,  g_khi);
    cudaGetSymbolAddress((void**)&vhi,  g_vhi);

    cudaFuncSetAttribute(gemm_mma<0>, cudaFuncAttributeMaxDynamicSharedMemorySize, GS_TOTAL);
    cudaFuncSetAttribute(gemm_mma<1>, cudaFuncAttributeMaxDynamicSharedMemorySize, GS_TOTAL);
    cudaFuncSetAttribute(gemm_mma<2>, cudaFuncAttributeMaxDynamicSharedMemorySize, GS_TOTAL);
    cudaFuncSetAttribute(flash_mma,   cudaFuncAttributeMaxDynamicSharedMemorySize, F_TOTAL);

    // one-time host objects (no device memory involved)
    static cudaStream_t s_kv = nullptr;
    static cudaEvent_t  evFork = nullptr, evJoin = nullptr;
    if (s_kv == nullptr) {
        cudaStreamCreateWithFlags(&s_kv, cudaStreamNonBlocking);
        cudaEventCreateWithFlags(&evFork, cudaEventDisableTiming);
        cudaEventCreateWithFlags(&evJoin, cudaEventDisableTiming);
    }
    const cudaStream_t s0 = 0;   // captured (legacy default) stream

    // x must precede both chains
    convw_s(s0, x, xh, (size_t)ROWS * DIM);

    // ---- fork: kv chain on s_kv
    cudaEventRecord(evFork, s0);
    cudaStreamWaitEvent(s_kv, evFork, 0);

    // kv chain (s_kv) — carries the wo convert too (only needed post-join)
    convw_s(s_kv, wkv_a, wka, (size_t)KVAW * DIM);
    convw_s(s_kv, wkv_b, wkb, (size_t)KV2W * KVLR);
    convw_s(s_kv, wo,    wo16,(size_t)DIM * OW);
    gemm_mma<0><<<dim3((KVAW + 127) / 128, ROWS / 128), 256, GS_TOTAL, s_kv>>>(
        xh, wka, p_kv, nullptr, nullptr, nullptr, KVAW, DIM, fcos, fsin);
    rmsnorm_h_kernel<<<ROWS, 256, 0, s_kv>>>(p_kv, kvnw, ckvnh, KVLR, KVAW);
    gemm_mma<2><<<dim3(KV2W / 128, ROWS / 128), 256, GS_TOTAL, s_kv>>>(
        ckvnh, wkb, nullptr, nullptr, khi, vhi, KV2W, KVLR, fcos, fsin);
    fill_kpe_kernel<<<ROWS, 256, 0, s_kv>>>(fcos, fsin);

    // q chain (s0)
    convw_s(s0, wq_a, wqa, (size_t)QLR * DIM);
    convw_s(s0, wq_b, wqb, (size_t)QW * QLR);
    gemm_mma<0><<<dim3(QLR / 128, ROWS / 128), 256, GS_TOTAL, s0>>>(
        xh, wqa, p_qa, nullptr, nullptr, nullptr, QLR, DIM, fcos, fsin);
    rmsnorm_h_kernel<<<ROWS, 256, 0, s0>>>(p_qa, qnw, qanh, QLR, QLR);
    gemm_mma<1><<<dim3(QW / 128, ROWS / 128), 256, GS_TOTAL, s0>>>(
        qanh, wqb, nullptr, qh, nullptr, nullptr, QW, QLR, fcos, fsin);

    // ---- join: flash needs both chains
    cudaEventRecord(evJoin, s_kv);
    cudaStreamWaitEvent(s0, evJoin, 0);

    // attention (tensor-core flash, occ 3)
    flash_mma<<<dim3(SEQ / 64, NH, BSZ), 128, F_TOTAL, s0>>>(qh, khi, vhi);

    // output projection
    gemm_mma<0><<<dim3(DIM / 128, ROWS / 128), 256, GS_TOTAL, s0>>>(
        ath, wo16, out, nullptr, nullptr, nullptr, DIM, OW, fcos, fsin);
}

// round 16
// speedup vs baseline: 1.2421x; 1.0533x over previous
#include <cuda_runtime.h>
#include <cuda_fp16.h>
#include <cstdint>
#include <math.h>

// Problem constants
#define BSZ   2
#define SEQ   2048
#define DIM   2048
#define NH    16
#define DRr   64
#define DNn   64
#define DQK   128
#define DVv   128
#define QLR   1536
#define KVLR  1024
#define ROWS  (BSZ*SEQ)          // 4096
#define KVAW  (KVLR + DRr)       // 1088
#define KV2W  (NH*(DNn+DVv))     // 3072
#define QW    (NH*DQK)           // 2048
#define OW    (NH*DVv)           // 2048

// -------- fp32 scratch --------
__device__ float g_qa  [ (size_t)ROWS * QLR  ];
__device__ float g_kv  [ (size_t)ROWS * KVAW ];

// -------- fp16 operands --------
__device__ __half g_xh   [(size_t)ROWS*DIM];
__device__ __half g_wqa  [(size_t)QLR*DIM];
__device__ __half g_wqb  [(size_t)QW*QLR];
__device__ __half g_wkva [(size_t)KVAW*DIM];
__device__ __half g_wkvb [(size_t)KV2W*KVLR];
__device__ __half g_wo16 [(size_t)DIM*OW];
__device__ __half g_qanh [(size_t)ROWS*QLR];
__device__ __half g_ckvnh[(size_t)ROWS*KVLR];
__device__ __half g_ath  [(size_t)ROWS*OW];
__device__ __half g_qh   [(size_t)ROWS*QW];
__device__ __half g_khi  [(size_t)ROWS*QW];
__device__ __half g_vhi  [(size_t)ROWS*OW];

// ============================================================
// helpers (sm_80-compatible instructions only — plain sm_103 target!)
// ============================================================
__device__ __forceinline__ uint32_t smem_u32(const void* p) {
    uint32_t a;
    asm("{ .reg .u64 t; cvta.to.shared.u64 t, %1; cvt.u32.u64 %0, t; }" : "=r"(a) : "l"(p));
    return a;
}

#define CP16(dst, src) \
    asm volatile("cp.async.cg.shared.global [%0], [%1], 16;" :: "r"(dst), "l"(src))
#define CP_COMMIT() asm volatile("cp.async.commit_group;" ::: "memory")
#define CP_WAIT(n)  asm volatile("cp.async.wait_group %0;" :: "n"(n) : "memory")

#define LDSM4(r0, r1, r2, r3, addr) \
    asm volatile("ldmatrix.sync.aligned.m8n8.x4.shared.b16 {%0,%1,%2,%3}, [%4];" \
        : "=r"(r0), "=r"(r1), "=r"(r2), "=r"(r3) : "r"(addr))

#define LDSM4T(r0, r1, r2, r3, addr) \
    asm volatile("ldmatrix.sync.aligned.m8n8.x4.trans.shared.b16 {%0,%1,%2,%3}, [%4];" \
        : "=r"(r0), "=r"(r1), "=r"(r2), "=r"(r3) : "r"(addr))

#define MMA_F16(d, a, b0, b1) \
    asm volatile("mma.sync.aligned.m16n8k16.row.col.f32.f16.f16.f32 " \
        "{%0,%1,%2,%3},{%4,%5,%6,%7},{%8,%9},{%0,%1,%2,%3};" \
        : "+f"((d)[0]), "+f"((d)[1]), "+f"((d)[2]), "+f"((d)[3]) \
        : "r"((a)[0]), "r"((a)[1]), "r"((a)[2]), "r"((a)[3]), "r"(b0), "r"(b1))

// ============================================================
// elementwise kernels (vectorized: 4 elems/thread)
// ============================================================
__global__ void conv_h4_kernel(const float4* __restrict__ in, uint2* __restrict__ out, int n4)
{
    int i = blockIdx.x * blockDim.x + threadIdx.x;
    if (i < n4) {
        float4 v = in[i];
        __half2 h0 = __floats2half2_rn(v.x, v.y);
        __half2 h1 = __floats2half2_rn(v.z, v.w);
        out[i] = make_uint2(*(uint32_t*)&h0, *(uint32_t*)&h1);
    }
}

// RMSNorm: fp32 in (strided) -> fp16 out, vectorized
__global__ void rmsnorm_h_kernel(const float* __restrict__ in, const float* __restrict__ w,
                                 __half* __restrict__ out, int K, int inStride)
{
    const int row = blockIdx.x;
    const float4* ip4 = (const float4*)(in + (size_t)row * inStride);
    const float4* w4  = (const float4*)w;
    uint2* op4 = (uint2*)(out + (size_t)row * K);
    const int K4 = K >> 2;

    float ss = 0.f;
    for (int i = threadIdx.x; i < K4; i += blockDim.x) {
        float4 v = ip4[i];
        ss += v.x * v.x + v.y * v.y + v.z * v.z + v.w * v.w;
    }
#pragma unroll
    for (int o = 16; o; o >>= 1) ss += __shfl_xor_sync(0xffffffffu, ss, o);

    __shared__ float red[8];
    __shared__ float rs;
    int wid = threadIdx.x >> 5, lid = threadIdx.x & 31;
    if (lid == 0) red[wid] = ss;
    __syncthreads();
    if (threadIdx.x == 0) {
        float t = 0.f;
        for (int i = 0; i < 8; i++) t += red[i];
        rs = rsqrtf(t / (float)K + 1e-6f);
    }
    __syncthreads();
    float r = rs;
    for (int i = threadIdx.x; i < K4; i += blockDim.x) {
        float4 v = ip4[i];
        float4 ww = w4[i];
        __half2 h0 = __floats2half2_rn(v.x * r * ww.x, v.y * r * ww.y);
        __half2 h1 = __floats2half2_rn(v.z * r * ww.z, v.w * r * ww.w);
        op4[i] = make_uint2(*(uint32_t*)&h0, *(uint32_t*)&h1);
    }
}

// Fill rotated k_pe into g_khi cols [h*128+64, h*128+128) for all heads.
__global__ void fill_kpe_kernel(const float* __restrict__ fcos, const float* __restrict__ fsin)
{
    const int row = blockIdx.x;
    const int tid = threadIdx.x;        // 256
    __shared__ float pe[64];
    const int s = row & (SEQ - 1);
    if (tid < 32) {
        float x0 = g_kv[(size_t)row * KVAW + KVLR + 2 * tid];
        float x1 = g_kv[(size_t)row * KVAW + KVLR + 2 * tid + 1];
        float c = fcos[s * 32 + tid], sn = fsin[s * 32 + tid];
        pe[2 * tid]     = x0 * c - x1 * sn;
        pe[2 * tid + 1] = x0 * sn + x1 * c;
    }
    __syncthreads();
#pragma unroll
    for (int l = 0; l < 2; l++) {
        int idx = tid + l * 256;        // 0..511: h = idx>>5, pair = idx&31
        int h = idx >> 5, pr = idx & 31;
        *(__half2*)&g_khi[(size_t)row * QW + h * DQK + DNn + 2 * pr] =
            __floats2half2_rn(pe[2 * pr], pe[2 * pr + 1]);
    }
}

// ============================================================
// single-term fp16 GEMM via mma.sync: C = A[M,K] @ W[N,K]^T
// 128x128x32 tiles, 4-stage cp.async pipeline, 8 warps (4m x 2n), occ 2.
// EPI = 0: fp32 C row-major (bounds-checked)
// EPI = 1: fused RoPE on d>=64 of each 128-head-slice + fp16 -> Hq (N=2048)
// EPI = 2: fused scatter of kv2 cols -> Hk (k_nope) / Hv (v), fp16 (N=3072)
// ============================================================
#define GBM 128
#define GBN 128
#define ROWB 80
#define MAT_BYTES (128 * ROWB)         // 10240
#define OFF_A   0
#define OFF_W   (1 * MAT_BYTES)
#define STAGE_BYTES (2 * MAT_BYTES)    // 20480
#define NSTAGE 4
#define GS_TOTAL (NSTAGE * STAGE_BYTES) // 81920

template<int EPI>
__global__ void __launch_bounds__(256, 2)
gemm_mma(const __half* __restrict__ A, const __half* __restrict__ W,
         float* __restrict__ C, __half* __restrict__ Hq,
         __half* __restrict__ Hk, __half* __restrict__ Hv,
         int N, int K,
         const float* __restrict__ fcos, const float* __restrict__ fsin)
{
    extern __shared__ char smx[];
    const uint32_t sb = smem_u32(smx);
    const int tid  = threadIdx.x;
    const int lane = tid & 31;
    const int warp = tid >> 5;
    const int wm = warp >> 1, wn = warp & 1;
    const int m0 = blockIdx.y * GBM;
    const int n0 = blockIdx.x * GBN;

    const int lrow = tid & 127;
    const int lc   = tid >> 7;
    const size_t a_g = (size_t)(m0 + lrow) * K;
    int wr = n0 + lrow; if (wr >= N) wr = N - 1;
    const size_t w_g = (size_t)wr * K;
    const uint32_t s_row = (uint32_t)lrow * ROWB;

    const uint32_t a_lm = (uint32_t)(wm * 32 + (lane & 15)) * ROWB + (uint32_t)(lane >> 4) * 16;
    const uint32_t b_lm = (uint32_t)(wn * 64 + (lane & 7) + ((lane >> 4) << 3)) * ROWB
                        + (uint32_t)((lane >> 3) & 1) * 16;

    float acc[2][8][4];
#pragma unroll
    for (int i = 0; i < 2; i++)
#pragma unroll
        for (int j = 0; j < 8; j++)
#pragma unroll
            for (int q = 0; q < 4; q++) acc[i][j][q] = 0.f;

    const int nch = K >> 5;

    // prologue: chunks 0..NSTAGE-2 into stages 0..NSTAGE-2
#pragma unroll
    for (int p = 0; p < NSTAGE - 1; p++) {
        const int k0 = p << 5;
        const uint32_t st = sb + p * STAGE_BYTES + s_row;
#pragma unroll
        for (int u = 0; u < 2; u++) {
            const int cc = lc + u * 2;
            CP16(st + OFF_A + cc * 16, A + a_g + k0 + cc * 8);
            CP16(st + OFF_W + cc * 16, W + w_g + k0 + cc * 8);
        }
        CP_COMMIT();
    }

    int stage = 0;
    for (int c = 0; c < nch; c++) {
        CP_WAIT(NSTAGE - 2);
        __syncthreads();

        if (c + NSTAGE - 1 < nch) {
            const int k0 = (c + NSTAGE - 1) << 5;
            int ws = stage + NSTAGE - 1; if (ws >= NSTAGE) ws -= NSTAGE;
            const uint32_t st = sb + ws * STAGE_BYTES + s_row;
#pragma unroll
            for (int u = 0; u < 2; u++) {
                const int cc = lc + u * 2;
                CP16(st + OFF_A + cc * 16, A + a_g + k0 + cc * 8);
                CP16(st + OFF_W + cc * 16, W + w_g + k0 + cc * 8);
            }
        }
        CP_COMMIT();

        const uint32_t base = sb + stage * STAGE_BYTES;
#pragma unroll
        for (int kk = 0; kk < 2; kk++) {
            uint32_t a[2][4], bh[4][4];
#pragma unroll
            for (int i = 0; i < 2; i++) {
                const uint32_t ao = base + OFF_A + a_lm + i * (16 * ROWB) + kk * 32;
                LDSM4(a[i][0], a[i][1], a[i][2], a[i][3], ao);
            }
#pragma unroll
            for (int g = 0; g < 4; g++) {
                const uint32_t bo = base + OFF_W + b_lm + g * (16 * ROWB) + kk * 32;
                LDSM4(bh[g][0], bh[g][1], bh[g][2], bh[g][3], bo);
            }
#pragma unroll
            for (int i = 0; i < 2; i++) {
#pragma unroll
                for (int j = 0; j < 8; j++) {
                    const int g = j >> 1, h = (j & 1) * 2;
                    MMA_F16(acc[i][j], a[i], bh[g][h], bh[g][h + 1]);
                }
            }
        }
        if (++stage == NSTAGE) stage = 0;
    }

    // ---- epilogue ----
#pragma unroll
    for (int i = 0; i < 2; i++) {
        const int row  = m0 + wm * 32 + i * 16 + (lane >> 2);
        const int row2 = row + 8;
#pragma unroll
        for (int j = 0; j < 8; j++) {
            const int col = n0 + wn * 64 + j * 8 + 2 * (lane & 3);
            float a0 = acc[i][j][0], a1 = acc[i][j][1];
            float b0 = acc[i][j][2], b1 = acc[i][j][3];

            if (EPI == 0) {
                if (col < N) {
                    *(float2*)&C[(size_t)row  * N + col] = make_float2(a0, a1);
                    *(float2*)&C[(size_t)row2 * N + col] = make_float2(b0, b1);
                }
            } else if (EPI == 1) {
                const int d = col & 127;
                if (d >= DNn) {
                    const int ir = (d - DNn) >> 1;
                    const int s0 = row & (SEQ - 1), s1 = row2 & (SEQ - 1);
                    float c0 = fcos[s0 * 32 + ir], sn0 = fsin[s0 * 32 + ir];
                    float c1 = fcos[s1 * 32 + ir], sn1 = fsin[s1 * 32 + ir];
                    float t0 = a0 * c0 - a1 * sn0, t1 = a0 * sn0 + a1 * c0;
                    a0 = t0; a1 = t1;
                    t0 = b0 * c1 - b1 * sn1; t1 = b0 * sn1 + b1 * c1;
                    b0 = t0; b1 = t1;
                }
                *(__half2*)&Hq[(size_t)row  * QW + col] = __floats2half2_rn(a0, a1);
                *(__half2*)&Hq[(size_t)row2 * QW + col] = __floats2half2_rn(b0, b1);
            } else {
                const int h = col / (DNn + DVv);
                const int d = col - h * (DNn + DVv);
                if (d < DNn) {
                    const size_t off = (size_t)h * DQK + d;
                    *(__half2*)&Hk[(size_t)row  * QW + off] = __floats2half2_rn(a0, a1);
                    *(__half2*)&Hk[(size_t)row2 * QW + off] = __floats2half2_rn(b0, b1);
                } else {
                    const size_t off = (size_t)h * DVv + (d - DNn);
                    *(__half2*)&Hv[(size_t)row  * OW + off] = __floats2half2_rn(a0, a1);
                    *(__half2*)&Hv[(size_t)row2 * OW + off] = __floats2half2_rn(b0, b1);
                }
            }
        }
    }
}

// ============================================================
// Flash attention — FA2-style, fp16 mma.sync, occupancy 3
// BQ=64, BK=64, 4 warps (each owns 16 rows), block 128.
// Batch passed as arg so the two batches can run on separate streams.
// grid: (SEQ/64, NH, 1)
// ============================================================
#define RB 272
#define SK    0
#define SV    17408
#define FSTG  34816                   // per stage: K + V
#define F_TOTAL (2 * FSTG)            // 69632

__global__ void __launch_bounds__(128, 3)
flash_mma(const __half* __restrict__ q16,
          const __half* __restrict__ khi, const __half* __restrict__ vhi, int b)
{
    extern __shared__ char smx[];
    const uint32_t sb = smem_u32(smx);
    const int tid = threadIdx.x, lane = tid & 31, wid = tid >> 5;   // 4 warps
    const int q0 = blockIdx.x * 64;
    const int h  = blockIdx.y;
    const float scale = 0.088388347648318447f;  // 128^-0.5

    const uint32_t a_off  = (uint32_t)(wid * 16 + (lane & 15)) * RB + (uint32_t)(lane >> 4) * 16;
    const uint32_t bK_off = (uint32_t)((lane & 7) + ((lane >> 4) << 3)) * RB
                          + (uint32_t)((lane >> 3) & 1) * 16;
    const uint32_t bV_off = (uint32_t)((lane & 7) + (((lane >> 3) & 1) << 3)) * RB
                          + (uint32_t)(lane >> 4) * 16;

    // ---- stage Q tile (64 x 128) through smem stage-0, hoist fragments
    {
        int r = tid >> 4;
        const int cc = tid & 15;
#pragma unroll
        for (int it = 0; it < 8; it++, r += 8) {
            size_t go = (size_t)(b * SEQ + q0 + r) * QW + h * DQK + cc * 8;
            *(uint4*)(smx + (uint32_t)r * RB + cc * 16) = *(const uint4*)(q16 + go);
        }
    }
    __syncthreads();
    uint32_t aq[8][4];
#pragma unroll
    for (int kk = 0; kk < 8; kk++)
        LDSM4(aq[kk][0], aq[kk][1], aq[kk][2], aq[kk][3], sb + a_off + kk * 32);
    __syncthreads();

    float oacc[16][4];
#pragma unroll
    for (int t = 0; t < 16; t++)
#pragma unroll
        for (int qq = 0; qq < 4; qq++) oacc[t][qq] = 0.f;
    float m0 = -1e30f, m1 = -1e30f, l0 = 0.f, l1 = 0.f;

    const int row0 = q0 + wid * 16 + (lane >> 2);
    const int row1 = row0 + 8;

    const int nkt = blockIdx.x + 1;
    const int ldr_r0 = tid >> 4;        // 8 rows per pass, 8 passes
    const int ldr_c  = tid & 15;

    // prologue: tiles 0,1 into stages 0,1 (empty commit when nkt==1)
#pragma unroll
    for (int p = 0; p < 2; p++) {
        if (p < nkt) {
            const uint32_t stg = sb + p * FSTG;
            int r = ldr_r0;
#pragma unroll
            for (int it = 0; it < 8; it++, r += 8) {
                size_t grow = (size_t)(b * SEQ + p * 64 + r);
                size_t gk = grow * QW + h * DQK + ldr_c * 8;
                size_t gv = grow * OW + h * DVv + ldr_c * 8;
                uint32_t so = (uint32_t)r * RB + ldr_c * 16;
                CP16(stg + SK + so, khi + gk);
                CP16(stg + SV + so, vhi + gv);
            }
        }
        CP_COMMIT();
    }

    int stage = 0;
    for (int kt = 0; kt < nkt; kt++) {
        const int t0 = kt * 64;
        CP_WAIT(1);                    // tile kt resident
        __syncthreads();               // make it visible to all warps

        const uint32_t stg = sb + stage * FSTG;

        // ---- S = Q @ K^T  (warp tile 16 x 64)
        float sacc[8][4];
#pragma unroll
        for (int t = 0; t < 8; t++)
#pragma unroll
            for (int qq = 0; qq < 4; qq++) sacc[t][qq] = 0.f;

#pragma unroll
        for (int kk = 0; kk < 8; kk++) {
#pragma unroll
            for (int g = 0; g < 4; g++) {
                uint32_t bh[4];
                const uint32_t bo = bK_off + g * (16 * RB) + kk * 32;
                LDSM4(bh[0], bh[1], bh[2], bh[3], stg + SK + bo);
                MMA_F16(sacc[2*g],   aq[kk], bh[0], bh[1]);
                MMA_F16(sacc[2*g+1], aq[kk], bh[2], bh[3]);
            }
        }

        // ---- scale + causal mask
        const int cb = t0 + 2 * (lane & 3);
#pragma unroll
        for (int t = 0; t < 8; t++) {
            const int c0 = cb + 8 * t, c1 = c0 + 1;
            sacc[t][0] = sacc[t][0] * scale + ((c0 > row0) ? -1e9f : 0.f);
            sacc[t][1] = sacc[t][1] * scale + ((c1 > row0) ? -1e9f : 0.f);
            sacc[t][2] = sacc[t][2] * scale + ((c0 > row1) ? -1e9f : 0.f);
            sacc[t][3] = sacc[t][3] * scale + ((c1 > row1) ? -1e9f : 0.f);
        }

        // ---- online softmax
        float mx0 = -1e30f, mx1 = -1e30f;
#pragma unroll
        for (int t = 0; t < 8; t++) {
            mx0 = fmaxf(mx0, fmaxf(sacc[t][0], sacc[t][1]));
            mx1 = fmaxf(mx1, fmaxf(sacc[t][2], sacc[t][3]));
        }
        mx0 = fmaxf(mx0, __shfl_xor_sync(0xffffffffu, mx0, 1));
        mx0 = fmaxf(mx0, __shfl_xor_sync(0xffffffffu, mx0, 2));
        mx1 = fmaxf(mx1, __shfl_xor_sync(0xffffffffu, mx1, 1));
        mx1 = fmaxf(mx1, __shfl_xor_sync(0xffffffffu, mx1, 2));

        const float mn0 = fmaxf(m0, mx0), mn1 = fmaxf(m1, mx1);
        const float al0 = __expf(m0 - mn0), al1 = __expf(m1 - mn1);
        m0 = mn0; m1 = mn1;

        float ps0 = 0.f, ps1 = 0.f;
#pragma unroll
        for (int t = 0; t < 8; t++) {
            sacc[t][0] = __expf(sacc[t][0] - mn0);
            sacc[t][1] = __expf(sacc[t][1] - mn0);
            sacc[t][2] = __expf(sacc[t][2] - mn1);
            sacc[t][3] = __expf(sacc[t][3] - mn1);
            ps0 += sacc[t][0] + sacc[t][1];
            ps1 += sacc[t][2] + sacc[t][3];
        }
        ps0 += __shfl_xor_sync(0xffffffffu, ps0, 1);
        ps0 += __shfl_xor_sync(0xffffffffu, ps0, 2);
        ps1 += __shfl_xor_sync(0xffffffffu, ps1, 1);
        ps1 += __shfl_xor_sync(0xffffffffu, ps1, 2);
        l0 = l0 * al0 + ps0;
        l1 = l1 * al1 + ps1;

#pragma unroll
        for (int t = 0; t < 16; t++) {
            oacc[t][0] *= al0; oacc[t][1] *= al0;
            oacc[t][2] *= al1; oacc[t][3] *= al1;
        }

        // ---- O += P @ V
#pragma unroll
        for (int jj = 0; jj < 4; jj++) {
            const int t2 = 2 * jj, t3 = 2 * jj + 1;
            uint32_t phi[4];
            {
                __half2 h0 = __floats2half2_rn(sacc[t2][0], sacc[t2][1]);
                __half2 h1 = __floats2half2_rn(sacc[t2][2], sacc[t2][3]);
                __half2 h2 = __floats2half2_rn(sacc[t3][0], sacc[t3][1]);
                __half2 h3 = __floats2half2_rn(sacc[t3][2], sacc[t3][3]);
                phi[0] = *(uint32_t*)&h0; phi[1] = *(uint32_t*)&h1;
                phi[2] = *(uint32_t*)&h2; phi[3] = *(uint32_t*)&h3;
            }
#pragma unroll
            for (int g = 0; g < 8; g++) {
                uint32_t bv[4];
                const uint32_t bo = bV_off + jj * (16 * RB) + g * 32;
                LDSM4T(bv[0], bv[1], bv[2], bv[3], stg + SV + bo);
                MMA_F16(oacc[2*g],   phi, bv[0], bv[1]);
                MMA_F16(oacc[2*g+1], phi, bv[2], bv[3]);
            }
        }

        // ---- stage fully consumed by ALL warps: now prefetch tile kt+2 into it
        __syncthreads();
        if (kt + 2 < nkt) {
            int r = ldr_r0;
#pragma unroll
            for (int it = 0; it < 8; it++, r += 8) {
                size_t grow = (size_t)(b * SEQ + (kt + 2) * 64 + r);
                size_t gk = grow * QW + h * DQK + ldr_c * 8;
                size_t gv = grow * OW + h * DVv + ldr_c * 8;
                uint32_t so = stg + (uint32_t)r * RB + ldr_c * 16;
                CP16(so + SK, khi + gk);
                CP16(so + SV, vhi + gv);
            }
        }
        CP_COMMIT();
        stage ^= 1;
    }

    // ---- epilogue: write fp16 attn directly (A operand of final GEMM)
    const float inv0 = 1.f / l0, inv1 = 1.f / l1;
    const size_t o0 = (size_t)(b * SEQ + row0) * OW + h * DVv;
    const size_t o1 = (size_t)(b * SEQ + row1) * OW + h * DVv;
#pragma unroll
    for (int t = 0; t < 16; t++) {
        const int d0 = 8 * t + 2 * (lane & 3);
        __half2 v0 = __floats2half2_rn(oacc[t][0] * inv0, oacc[t][1] * inv0);
        __half2 v1 = __floats2half2_rn(oacc[t][2] * inv1, oacc[t][3] * inv1);
        *(__half2*)&g_ath[o0 + d0] = v0;
        *(__half2*)&g_ath[o1 + d0] = v1;
    }
}

// ============================================================
// launch — q/kv chains forked on two streams; flash + output projection
// also split by batch across the two streams.
// ============================================================
static inline void convw_s(cudaStream_t s, const float* in, __half* out, size_t n)
{
    conv_h4_kernel<<<(int)((n / 4 + 255) / 256), 256, 0, s>>>(
        (const float4*)in, (uint2*)out, (int)(n / 4));
}

extern "C" void kernel_launch(void* const* d_in, const int* in_sizes, int n_in,
                              void* d_out, int out_size)
{
    const float* x      = (const float*)d_in[0];
    const float* wq_a   = (const float*)d_in[1];
    const float* qnw    = (const float*)d_in[2];
    const float* wq_b   = (const float*)d_in[3];
    const float* wkv_a  = (const float*)d_in[4];
    const float* kvnw   = (const float*)d_in[5];
    const float* wkv_b  = (const float*)d_in[6];
    const float* wo     = (const float*)d_in[7];
    const float* fcos   = (const float*)d_in[9];
    const float* fsin   = (const float*)d_in[10];

    float* out = (float*)d_out;

    float *p_qa, *p_kv;
    cudaGetSymbolAddress((void**)&p_qa,   g_qa);
    cudaGetSymbolAddress((void**)&p_kv,   g_kv);

    __half *xh, *wqa, *wqb, *wka, *wkb, *wo16, *qanh, *ckvnh, *ath, *qh, *khi, *vhi;
    cudaGetSymbolAddress((void**)&xh,   g_xh);
    cudaGetSymbolAddress((void**)&wqa,  g_wqa);
    cudaGetSymbolAddress((void**)&wqb,  g_wqb);
    cudaGetSymbolAddress((void**)&wka,  g_wkva);
    cudaGetSymbolAddress((void**)&wkb,  g_wkvb);
    cudaGetSymbolAddress((void**)&wo16, g_wo16);
    cudaGetSymbolAddress((void**)&qanh, g_qanh);
    cudaGetSymbolAddress((void**)&ckvnh,g_ckvnh);
    cudaGetSymbolAddress((void**)&ath,  g_ath);
    cudaGetSymbolAddress((void**)&qh,   g_qh);
    cudaGetSymbolAddress((void**)&khi,  g_khi);
    cudaGetSymbolAddress((void**)&vhi,  g_vhi);

    cudaFuncSetAttribute(gemm_mma<0>, cudaFuncAttributeMaxDynamicSharedMemorySize, GS_TOTAL);
    cudaFuncSetAttribute(gemm_mma<1>, cudaFuncAttributeMaxDynamicSharedMemorySize, GS_TOTAL);
    cudaFuncSetAttribute(gemm_mma<2>, cudaFuncAttributeMaxDynamicSharedMemorySize, GS_TOTAL);
    cudaFuncSetAttribute(flash_mma,   cudaFuncAttributeMaxDynamicSharedMemorySize, F_TOTAL);

    // one-time host objects (no device memory involved)
    static cudaStream_t s_kv = nullptr;
    static cudaEvent_t  evFork = nullptr, evJoin = nullptr, evQ = nullptr, evEnd = nullptr;
    if (s_kv == nullptr) {
        cudaStreamCreateWithFlags(&s_kv, cudaStreamNonBlocking);
        cudaEventCreateWithFlags(&evFork, cudaEventDisableTiming);
        cudaEventCreateWithFlags(&evJoin, cudaEventDisableTiming);
        cudaEventCreateWithFlags(&evQ,    cudaEventDisableTiming);
        cudaEventCreateWithFlags(&evEnd,  cudaEventDisableTiming);
    }
    const cudaStream_t s0 = 0;   // captured (legacy default) stream

    // x must precede both chains
    convw_s(s0, x, xh, (size_t)ROWS * DIM);

    // ---- fork: kv chain on s_kv
    cudaEventRecord(evFork, s0);
    cudaStreamWaitEvent(s_kv, evFork, 0);

    // kv chain (s_kv) — carries the wo convert too (only needed post-join)
    convw_s(s_kv, wkv_a, wka, (size_t)KVAW * DIM);
    convw_s(s_kv, wkv_b, wkb, (size_t)KV2W * KVLR);
    convw_s(s_kv, wo,    wo16,(size_t)DIM * OW);
    gemm_mma<0><<<dim3((KVAW + 127) / 128, ROWS / 128), 256, GS_TOTAL, s_kv>>>(
        xh, wka, p_kv, nullptr, nullptr, nullptr, KVAW, DIM, fcos, fsin);
    rmsnorm_h_kernel<<<ROWS, 256, 0, s_kv>>>(p_kv, kvnw, ckvnh, KVLR, KVAW);
    gemm_mma<2><<<dim3(KV2W / 128, ROWS / 128), 256, GS_TOTAL, s_kv>>>(
        ckvnh, wkb, nullptr, nullptr, khi, vhi, KV2W, KVLR, fcos, fsin);
    fill_kpe_kernel<<<ROWS, 256, 0, s_kv>>>(fcos, fsin);

    // q chain (s0)
    convw_s(s0, wq_a, wqa, (size_t)QLR * DIM);
    convw_s(s0, wq_b, wqb, (size_t)QW * QLR);
    gemm_mma<0><<<dim3(QLR / 128, ROWS / 128), 256, GS_TOTAL, s0>>>(
        xh, wqa, p_qa, nullptr, nullptr, nullptr, QLR, DIM, fcos, fsin);
    rmsnorm_h_kernel<<<ROWS, 256, 0, s0>>>(p_qa, qnw, qanh, QLR, QLR);
    gemm_mma<1><<<dim3(QW / 128, ROWS / 128), 256, GS_TOTAL, s0>>>(
        qanh, wqb, nullptr, qh, nullptr, nullptr, QW, QLR, fcos, fsin);

    // ---- cross-stream deps for the batch-split tail
    cudaEventRecord(evQ, s0);          // q ready
    cudaStreamWaitEvent(s_kv, evQ, 0); // s_kv: has kv (own) + q
    cudaEventRecord(evJoin, s_kv);     // kv ready
    cudaStreamWaitEvent(s0, evJoin, 0);// s0: has q (own) + kv

    // batch 0 on s0, batch 1 on s_kv: flash then its half of the projection
    flash_mma<<<dim3(SEQ / 64, NH, 1), 128, F_TOTAL, s0>>>(qh, khi, vhi, 0);
    flash_mma<<<dim3(SEQ / 64, NH, 1), 128, F_TOTAL, s_kv>>>(qh, khi, vhi, 1);

    gemm_mma<0><<<dim3(DIM / 128, SEQ / 128), 256, GS_TOTAL, s0>>>(
        ath, wo16, out, nullptr, nullptr, nullptr, DIM, OW, fcos, fsin);
    gemm_mma<0><<<dim3(DIM / 128, SEQ / 128), 256, GS_TOTAL, s_kv>>>(
        ath + (size_t)SEQ * OW, wo16, out + (size_t)SEQ * DIM,
        nullptr, nullptr, nullptr, DIM, OW, fcos, fsin);

    // ---- final join back to the captured stream
    cudaEventRecord(evEnd, s_kv);
    cudaStreamWaitEvent(s0, evEnd, 0);
}